// round 5
// baseline (speedup 1.0000x reference)
#include <cuda_runtime.h>
#include <cstdint>
#include <cfloat>

#define BROWS 8192
#define DIM   2048
#define NBLK  (BROWS/128)

#define BM 128
#define BN 256
#define BK 32
#define NCH (DIM/BK)            // 64 k-iterations
// padded smem tiles (uint32 words): As[128][36], Bs[32][264]
#define A_SM_WORDS 36
#define B_SM_WORDS 264
#define A_SM_BYTES (128*A_SM_WORDS*4)   // 18432
#define B_SM_BYTES (32*B_SM_WORDS*4)    // 33792
#define STAGE_BYTES (A_SM_BYTES + B_SM_BYTES)  // 52224
#define NSTAGE 4
#define SMEM_TOTAL (NSTAGE*STAGE_BYTES)        // 208896

#define NTHREADS 256            // 8 warps, 2x4 grid of 64x64 warp tiles

// ------------------------- persistent device scratch -------------------------
__device__ __align__(16) float g_X[(size_t)BROWS * DIM];        // tf32-rounded x
__device__ __align__(16) float g_W[(size_t)4 * DIM * DIM];      // tf32-rounded W ([l][k][n])
__device__ __align__(16) float g_H0[(size_t)BROWS * DIM];
__device__ __align__(16) float g_H1[(size_t)BROWS * DIM];
__device__ __align__(16) float g_H2[(size_t)BROWS * DIM];
__device__ int   g_route[BROWS];
__device__ int   g_need1[NBLK];
__device__ int   g_need2[NBLK];

// ------------------------------- helpers --------------------------------
__device__ __forceinline__ uint32_t smem_u32(const void* p) {
    uint32_t a;
    asm("{ .reg .u64 t; cvta.to.shared.u64 t, %1; cvt.u32.u64 %0, t; }" : "=r"(a) : "l"(p));
    return a;
}
__device__ __forceinline__ uint32_t f2tf32(float x) {
    uint32_t y; asm("cvt.rna.tf32.f32 %0, %1;" : "=r"(y) : "f"(x)); return y;
}
#define CP_ASYNC16(dst, src) \
    asm volatile("cp.async.cg.shared.global [%0], [%1], 16;" :: "r"(dst), "l"(src) : "memory")

__device__ __forceinline__ float gelu_f(float x) {
    float x3 = x * x * x;
    float t = tanhf(0.7978845608028654f * (x + 0.044715f * x3));
    return 0.5f * x * (1.f + t);
}

// ---------------------------------------------------------------------------
// Fused: min/max + router MLP + flags. Single block, 1024 threads.
// ---------------------------------------------------------------------------
__global__ __launch_bounds__(1024)
void route_fused_kernel(const float* __restrict__ unc,
                        const float* __restrict__ rw1, const float* __restrict__ rb1,
                        const float* __restrict__ rw2, const float* __restrict__ rb2,
                        const float* __restrict__ rw3, const float* __restrict__ rb3,
                        float* __restrict__ out_mask) {
    __shared__ float smin[1024], smax[1024];
    __shared__ float s_w1[32], s_b1[32], s_w2[512], s_b2[16], s_w3[48], s_b3[3];
    __shared__ float s_mn, s_mx;
    int t = threadIdx.x;

    if (t < 32) { s_w1[t] = rw1[t]; s_b1[t] = rb1[t]; }
    if (t >= 256 && t < 768) s_w2[t - 256] = rw2[t - 256];
    if (t >= 768 && t < 784) s_b2[t - 768] = rb2[t - 768];
    if (t >= 800 && t < 848) s_w3[t - 800] = rw3[t - 800];
    if (t >= 864 && t < 867) s_b3[t - 864] = rb3[t - 864];

    float mn = FLT_MAX, mx = -FLT_MAX;
    for (int i = t; i < BROWS; i += 1024) {
        float v = unc[i];
        mn = fminf(mn, v); mx = fmaxf(mx, v);
    }
    smin[t] = mn; smax[t] = mx;
    __syncthreads();
    for (int s = 512; s > 0; s >>= 1) {
        if (t < s) {
            smin[t] = fminf(smin[t], smin[t + s]);
            smax[t] = fmaxf(smax[t], smax[t + s]);
        }
        __syncthreads();
    }
    if (t == 0) { s_mn = smin[0]; s_mx = smax[0]; }
    if (t < NBLK) { g_need1[t] = 0; g_need2[t] = 0; }
    __syncthreads();

    float vmn = s_mn, vmx = s_mx;
    for (int i = t; i < BROWS; i += 1024) {
        float u = (unc[i] - vmn) / (vmx - vmn + 1e-8f);
        float h1[32];
#pragma unroll
        for (int j = 0; j < 32; j++) h1[j] = fmaxf(fmaf(u, s_w1[j], s_b1[j]), 0.f);
        float h2[16];
#pragma unroll
        for (int j = 0; j < 16; j++) {
            float a = s_b2[j];
#pragma unroll
            for (int k = 0; k < 32; k++) a = fmaf(h1[k], s_w2[k * 16 + j], a);
            h2[j] = fmaxf(a, 0.f);
        }
        float l[3];
#pragma unroll
        for (int j = 0; j < 3; j++) {
            float a = s_b3[j];
#pragma unroll
            for (int k = 0; k < 16; k++) a = fmaf(h2[k], s_w3[k * 3 + j], a);
            l[j] = a;
        }
        int r = 0; float best = l[0];
        if (l[1] > best) { best = l[1]; r = 1; }
        if (l[2] > best) { best = l[2]; r = 2; }
        g_route[i]  = r;
        out_mask[i] = (float)r;
        if (r >= 1) atomicOr(&g_need1[i >> 7], 1);
        if (r == 2) atomicOr(&g_need2[i >> 7], 1);
    }
}

// ---------------------------------------------------------------------------
// prep: elementwise tf32 rounding of x and W
// ---------------------------------------------------------------------------
__global__ void convx_kernel(const float* __restrict__ x) {
    size_t i = ((size_t)blockIdx.x * 256 + threadIdx.x) * 4;
    float4 v = *(const float4*)(x + i);
    v.x = __uint_as_float(f2tf32(v.x)); v.y = __uint_as_float(f2tf32(v.y));
    v.z = __uint_as_float(f2tf32(v.z)); v.w = __uint_as_float(f2tf32(v.w));
    *(float4*)(g_X + i) = v;
}
__global__ void convw_kernel(const float* __restrict__ Ws) {
    size_t i = ((size_t)blockIdx.x * 256 + threadIdx.x) * 4;
    float4 v = *(const float4*)(Ws + i);
    v.x = __uint_as_float(f2tf32(v.x)); v.y = __uint_as_float(f2tf32(v.y));
    v.z = __uint_as_float(f2tf32(v.z)); v.w = __uint_as_float(f2tf32(v.w));
    *(float4*)(g_W + i) = v;
}

// ---------------------------------------------------------------------------
// TF32 mma.sync GEMM, 4-stage cp.async pipeline.
// CTA 128x256x32, 256 threads (8 warps 2x4), warp tile 64x64, m16n8k8.
// ---------------------------------------------------------------------------
__global__ __launch_bounds__(NTHREADS, 1)
void gemm_kernel(const float* __restrict__ ball, float* __restrict__ outp,
                 int layerIdx, int abuf, int hbuf, int outLevel, int needSel) {
    int bn = blockIdx.x, bm = blockIdx.y;
    if (needSel == 1 && !g_need1[bm]) return;
    if (needSel == 2 && !g_need2[bm]) return;

    extern __shared__ char smem[];
    uint32_t smem_base = smem_u32(smem);

    const float* A = (abuf == 0) ? g_X : (abuf == 1 ? g_H0 : (abuf == 2 ? g_H1 : g_H2));
    float* Hptr = (hbuf == 1) ? g_H0 : (hbuf == 2 ? g_H1 : (hbuf == 3 ? g_H2 : nullptr));
    const float* bias = ball + layerIdx * DIM;
    const char* aSrc = (const char*)(A + (size_t)bm * BM * DIM);
    const char* bSrc = (const char*)(g_W + (size_t)layerIdx * DIM * DIM + (size_t)bn * BN);

    int tid  = threadIdx.x;
    int warp = tid >> 5, lane = tid & 31;
    int wm = warp >> 2, wn = warp & 3;     // 2x4 warp grid, 64x64 per warp
    int gq = lane >> 2, tr = lane & 3;

    float acc[4][8][4];
#pragma unroll
    for (int i = 0; i < 4; i++)
#pragma unroll
        for (int j = 0; j < 8; j++)
#pragma unroll
            for (int r = 0; r < 4; r++) acc[i][j][r] = 0.f;

    // --- async load issuer: 12 x 16B cp.async per thread per stage ---
    auto issue = [&](int c) {
        int slot = c & (NSTAGE - 1);
        uint32_t ab = smem_base + slot * STAGE_BYTES;
        uint32_t bb = ab + A_SM_BYTES;
        // A tile: 128 rows x 8 granules (16B); padded row stride 144B
        #pragma unroll
        for (int i = 0; i < 4; i++) {
            int g = tid + i * NTHREADS;
            int r = g >> 3, gc = g & 7;
            CP_ASYNC16(ab + (uint32_t)(r * 144 + gc * 16),
                       aSrc + (size_t)r * (DIM * 4) + (size_t)c * (BK * 4) + gc * 16);
        }
        // B tile: 32 rows x 64 granules (16B); padded row stride 1056B
        #pragma unroll
        for (int i = 0; i < 8; i++) {
            int g = tid + i * NTHREADS;
            int r = g >> 6, gc = g & 63;
            CP_ASYNC16(bb + (uint32_t)(r * 1056 + gc * 16),
                       bSrc + (size_t)(c * BK + r) * (DIM * 4) + gc * 16);
        }
        asm volatile("cp.async.commit_group;" ::: "memory");
    };

    issue(0);
    issue(1);
    issue(2);

    for (int c = 0; c < NCH; c++) {
        if (c <= NCH - 3)      asm volatile("cp.async.wait_group 2;" ::: "memory");
        else if (c == NCH - 2) asm volatile("cp.async.wait_group 1;" ::: "memory");
        else                   asm volatile("cp.async.wait_group 0;" ::: "memory");
        __syncthreads();
        if (c + 3 < NCH) issue(c + 3);

        int slot = c & (NSTAGE - 1);
        const uint32_t* As = (const uint32_t*)(smem + slot * STAGE_BYTES);
        const uint32_t* Bs = (const uint32_t*)(smem + slot * STAGE_BYTES + A_SM_BYTES);

#pragma unroll
        for (int k8 = 0; k8 < BK; k8 += 8) {
            uint32_t af[4][4], bf[8][2];
#pragma unroll
            for (int i = 0; i < 4; i++) {
                int row = wm * 64 + i * 16 + gq;
                int col = k8 + tr;
                af[i][0] = As[row * A_SM_WORDS + col];
                af[i][1] = As[(row + 8) * A_SM_WORDS + col];
                af[i][2] = As[row * A_SM_WORDS + col + 4];
                af[i][3] = As[(row + 8) * A_SM_WORDS + col + 4];
            }
#pragma unroll
            for (int j = 0; j < 8; j++) {
                int coln = wn * 64 + j * 8 + gq;
                int rk = k8 + tr;
                bf[j][0] = Bs[rk * B_SM_WORDS + coln];
                bf[j][1] = Bs[(rk + 4) * B_SM_WORDS + coln];
            }
#pragma unroll
            for (int i = 0; i < 4; i++)
#pragma unroll
                for (int j = 0; j < 8; j++) {
                    asm volatile(
                        "mma.sync.aligned.m16n8k8.row.col.f32.tf32.tf32.f32 "
                        "{%0,%1,%2,%3}, {%4,%5,%6,%7}, {%8,%9}, {%0,%1,%2,%3};"
                        : "+f"(acc[i][j][0]), "+f"(acc[i][j][1]),
                          "+f"(acc[i][j][2]), "+f"(acc[i][j][3])
                        : "r"(af[i][0]), "r"(af[i][1]), "r"(af[i][2]), "r"(af[i][3]),
                          "r"(bf[j][0]), "r"(bf[j][1]));
                }
        }
        __syncthreads();
    }

    // ---- epilogue: bias + GELU; H stored tf32-rounded, routed rows -> out ----
    int rbase = bm * BM + wm * 64;
    int cbase = bn * BN + wn * 64;
#pragma unroll
    for (int i = 0; i < 4; i++) {
        int row0 = rbase + i * 16 + gq;
        int row1 = row0 + 8;
        int rt0 = g_route[row0], rt1 = g_route[row1];
#pragma unroll
        for (int j = 0; j < 8; j++) {
            int col = cbase + j * 8 + 2 * tr;
            float b0 = bias[col], b1 = bias[col + 1];
            float v00 = gelu_f(acc[i][j][0] + b0);
            float v01 = gelu_f(acc[i][j][1] + b1);
            float v10 = gelu_f(acc[i][j][2] + b0);
            float v11 = gelu_f(acc[i][j][3] + b1);
            if (Hptr) {
                float2 h0 = make_float2(__uint_as_float(f2tf32(v00)), __uint_as_float(f2tf32(v01)));
                float2 h1 = make_float2(__uint_as_float(f2tf32(v10)), __uint_as_float(f2tf32(v11)));
                *(float2*)&Hptr[(size_t)row0 * DIM + col] = h0;
                *(float2*)&Hptr[(size_t)row1 * DIM + col] = h1;
            }
            if (outp) {
                if (rt0 == outLevel) *(float2*)&outp[(size_t)row0 * DIM + col] = make_float2(v00, v01);
                if (rt1 == outLevel) *(float2*)&outp[(size_t)row1 * DIM + col] = make_float2(v10, v11);
            }
        }
    }
}

// ---------------------------------------------------------------------------
extern "C" void kernel_launch(void* const* d_in, const int* in_sizes, int n_in,
                              void* d_out, int out_size) {
    const float* x   = (const float*)d_in[0];
    const float* unc = (const float*)d_in[1];
    const float* Ws  = (const float*)d_in[2];
    const float* bs  = (const float*)d_in[3];
    const float* rw1 = (const float*)d_in[4];
    const float* rb1 = (const float*)d_in[5];
    const float* rw2 = (const float*)d_in[6];
    const float* rb2 = (const float*)d_in[7];
    const float* rw3 = (const float*)d_in[8];
    const float* rb3 = (const float*)d_in[9];

    float* out  = (float*)d_out;
    float* mask = out + (size_t)BROWS * DIM;

    cudaFuncSetAttribute(gemm_kernel, cudaFuncAttributeMaxDynamicSharedMemorySize, SMEM_TOTAL);

    // launch order chosen so the L0 GEMM sits at launch index 3 (ncu slot)
    route_fused_kernel<<<1, 1024>>>(unc, rw1, rb1, rw2, rb2, rw3, rb3, mask);
    convx_kernel<<<(BROWS * (DIM / 4)) / 256, 256>>>(x);
    convw_kernel<<<(4 * DIM * (DIM / 4)) / 256, 256>>>(Ws);

    dim3 grid(DIM / BN, BROWS / BM);  // (8, 64)
    // L0: in=g_X, H=g_H0, rows route==0 -> out
    gemm_kernel<<<grid, NTHREADS, SMEM_TOTAL>>>(bs, out,     0, 0, 1, 0,  0);
    // L1: in=H0, H=H1, rows route==1 -> out ; skip tiles with no route>=1
    gemm_kernel<<<grid, NTHREADS, SMEM_TOTAL>>>(bs, out,     1, 1, 2, 1,  1);
    // L2: in=H1, H=H2 ; skip tiles with no route==2
    gemm_kernel<<<grid, NTHREADS, SMEM_TOTAL>>>(bs, nullptr, 2, 2, 3, -1, 2);
    // L3: in=H2, rows route==2 -> out ; skip tiles with no route==2
    gemm_kernel<<<grid, NTHREADS, SMEM_TOTAL>>>(bs, out,     3, 3, 0, 2,  2);
}

// round 6
// speedup vs baseline: 1.1035x; 1.1035x over previous
#include <cuda_runtime.h>
#include <cstdint>
#include <cfloat>

#define BROWS 8192
#define DIM   2048

#define BM 128
#define BN 128
#define BK 32
#define NCH (DIM/BK)            // 64 k-iterations
#define A_SM_BYTES (128*36*4)   // 18432
#define B_SM_BYTES (32*136*4)   // 17408
#define STAGE_BYTES (A_SM_BYTES + B_SM_BYTES)  // 35840
#define NSTAGE 3
#define SMEM_TOTAL (NSTAGE*STAGE_BYTES)        // 107520

// ------------------------- persistent device scratch -------------------------
__device__ __align__(16) float g_X[(size_t)BROWS * DIM];        // tf32-rounded x (orig order)
__device__ __align__(16) float g_W[(size_t)4 * DIM * DIM];      // tf32-rounded W ([l][k][n])
__device__ __align__(16) float g_H0[(size_t)BROWS * DIM];       // compacted order
__device__ __align__(16) float g_H1[(size_t)BROWS * DIM];       // compacted order
__device__ __align__(16) float g_H2[(size_t)BROWS * DIM];       // compacted order
__device__ int g_route[BROWS];   // per original row: level 0/1/2
__device__ int g_perm[BROWS];    // compact pos -> orig row
__device__ int g_pos[BROWS];     // orig row -> compact pos
__device__ int g_lim[3];         // [0]=8192, [1]=ceil128(n1+n2), [2]=ceil128(n2)

// ------------------------------- helpers --------------------------------
__device__ __forceinline__ uint32_t smem_u32(const void* p) {
    uint32_t a;
    asm("{ .reg .u64 t; cvta.to.shared.u64 t, %1; cvt.u32.u64 %0, t; }" : "=r"(a) : "l"(p));
    return a;
}
__device__ __forceinline__ uint32_t f2tf32(float x) {
    uint32_t y; asm("cvt.rna.tf32.f32 %0, %1;" : "=r"(y) : "f"(x)); return y;
}
#define CP_ASYNC16(dst, src) \
    asm volatile("cp.async.cg.shared.global [%0], [%1], 16;" :: "r"(dst), "l"(src) : "memory")

__device__ __forceinline__ float gelu_f(float x) {
    float x3 = x * x * x;
    float t = tanhf(0.7978845608028654f * (x + 0.044715f * x3));
    return 0.5f * x * (1.f + t);
}

// ---------------------------------------------------------------------------
// Fused: min/max + router MLP + compaction permutation. One block, 1024 thr.
// ---------------------------------------------------------------------------
__global__ __launch_bounds__(1024)
void route_fused_kernel(const float* __restrict__ unc,
                        const float* __restrict__ rw1, const float* __restrict__ rb1,
                        const float* __restrict__ rw2, const float* __restrict__ rb2,
                        const float* __restrict__ rw3, const float* __restrict__ rb3,
                        float* __restrict__ out_mask) {
    __shared__ float smin[1024], smax[1024];
    __shared__ float s_w1[32], s_b1[32], s_w2[512], s_b2[16], s_w3[48], s_b3[3];
    __shared__ float s_mn, s_mx;
    __shared__ int s_cnt[3];     // histogram
    __shared__ int s_ctr[3];     // running per-class counters
    __shared__ int s_base[3];    // class base offsets (class = route level)
    int t = threadIdx.x;

    if (t < 32) { s_w1[t] = rw1[t]; s_b1[t] = rb1[t]; }
    if (t >= 256 && t < 768) s_w2[t - 256] = rw2[t - 256];
    if (t >= 768 && t < 784) s_b2[t - 768] = rb2[t - 768];
    if (t >= 800 && t < 848) s_w3[t - 800] = rw3[t - 800];
    if (t >= 864 && t < 867) s_b3[t - 864] = rb3[t - 864];
    if (t < 3) { s_cnt[t] = 0; s_ctr[t] = 0; }

    float mn = FLT_MAX, mx = -FLT_MAX;
    for (int i = t; i < BROWS; i += 1024) {
        float v = unc[i];
        mn = fminf(mn, v); mx = fmaxf(mx, v);
    }
    smin[t] = mn; smax[t] = mx;
    __syncthreads();
    for (int s = 512; s > 0; s >>= 1) {
        if (t < s) {
            smin[t] = fminf(smin[t], smin[t + s]);
            smax[t] = fmaxf(smax[t], smax[t + s]);
        }
        __syncthreads();
    }
    if (t == 0) { s_mn = smin[0]; s_mx = smax[0]; }
    __syncthreads();

    float vmn = s_mn, vmx = s_mx;
    for (int i = t; i < BROWS; i += 1024) {
        float u = (unc[i] - vmn) / (vmx - vmn + 1e-8f);
        float h1[32];
#pragma unroll
        for (int j = 0; j < 32; j++) h1[j] = fmaxf(fmaf(u, s_w1[j], s_b1[j]), 0.f);
        float h2[16];
#pragma unroll
        for (int j = 0; j < 16; j++) {
            float a = s_b2[j];
#pragma unroll
            for (int k = 0; k < 32; k++) a = fmaf(h1[k], s_w2[k * 16 + j], a);
            h2[j] = fmaxf(a, 0.f);
        }
        float l[3];
#pragma unroll
        for (int j = 0; j < 3; j++) {
            float a = s_b3[j];
#pragma unroll
            for (int k = 0; k < 16; k++) a = fmaf(h2[k], s_w3[k * 3 + j], a);
            l[j] = a;
        }
        int r = 0; float best = l[0];
        if (l[1] > best) { best = l[1]; r = 1; }
        if (l[2] > best) { best = l[2]; r = 2; }
        g_route[i]  = r;
        out_mask[i] = (float)r;
        atomicAdd(&s_cnt[r], 1);
    }
    __syncthreads();

    if (t == 0) {
        int n0 = s_cnt[0], n1 = s_cnt[1], n2 = s_cnt[2];
        // compact layout: [route2 | route1 | route0]
        s_base[2] = 0;
        s_base[1] = n2;
        s_base[0] = n2 + n1;
        int n12 = n1 + n2;
        g_lim[0] = BROWS;
        g_lim[1] = (n12 + 127) & ~127;
        g_lim[2] = (n2 + 127) & ~127;
        (void)n0;
    }
    __syncthreads();

    for (int i = t; i < BROWS; i += 1024) {
        int r = g_route[i];
        int pos = s_base[r] + atomicAdd(&s_ctr[r], 1);
        g_pos[i] = pos;
        g_perm[pos] = i;
    }
}

// ---------------------------------------------------------------------------
// prep: elementwise tf32 rounding of x and W
// ---------------------------------------------------------------------------
__global__ void convx_kernel(const float* __restrict__ x) {
    size_t i = ((size_t)blockIdx.x * 256 + threadIdx.x) * 4;
    float4 v = *(const float4*)(x + i);
    v.x = __uint_as_float(f2tf32(v.x)); v.y = __uint_as_float(f2tf32(v.y));
    v.z = __uint_as_float(f2tf32(v.z)); v.w = __uint_as_float(f2tf32(v.w));
    *(float4*)(g_X + i) = v;
}
__global__ void convw_kernel(const float* __restrict__ Ws) {
    size_t i = ((size_t)blockIdx.x * 256 + threadIdx.x) * 4;
    float4 v = *(const float4*)(Ws + i);
    v.x = __uint_as_float(f2tf32(v.x)); v.y = __uint_as_float(f2tf32(v.y));
    v.z = __uint_as_float(f2tf32(v.z)); v.w = __uint_as_float(f2tf32(v.w));
    *(float4*)(g_W + i) = v;
}

// ---------------------------------------------------------------------------
// TF32 mma.sync GEMM, 3-stage cp.async pipeline (proven 1637us config).
// CTA 128x128x32, 256 threads (8 warps 2x4), warp tile 64x32, m16n8k8.
//   compact=0: A rows are original order; H written scattered via g_pos.
//   compact=1: A rows are compact order; orig looked up via g_perm.
//   Early exit: CTAs with bm*BM >= g_lim[limSel] return.
//   H rows written only when dest row < g_lim[hLimSel].
// ---------------------------------------------------------------------------
__global__ __launch_bounds__(256, 2)
void gemm_kernel(const float* __restrict__ ball, float* __restrict__ outp,
                 int layerIdx, int abuf, int hbuf, int outLevel,
                 int compact, int limSel, int hLimSel) {
    int bn = blockIdx.x, bm = blockIdx.y;
    if (bm * BM >= g_lim[limSel]) return;

    extern __shared__ char smem[];
    uint32_t smem_base = smem_u32(smem);

    const float* A = (abuf == 0) ? g_X : (abuf == 1 ? g_H0 : (abuf == 2 ? g_H1 : g_H2));
    float* Hptr = (hbuf == 1) ? g_H0 : (hbuf == 2 ? g_H1 : (hbuf == 3 ? g_H2 : nullptr));
    const float* bias = ball + layerIdx * DIM;
    const char* aSrc = (const char*)(A + (size_t)bm * BM * DIM);
    const char* bSrc = (const char*)(g_W + (size_t)layerIdx * DIM * DIM + (size_t)bn * BN);

    int tid  = threadIdx.x;
    int warp = tid >> 5, lane = tid & 31;
    int wm = warp >> 2, wn = warp & 3;
    int gq = lane >> 2, tr = lane & 3;

    float acc[4][4][4];
#pragma unroll
    for (int i = 0; i < 4; i++)
#pragma unroll
        for (int j = 0; j < 4; j++)
#pragma unroll
            for (int r = 0; r < 4; r++) acc[i][j][r] = 0.f;

    auto issue = [&](int c) {
        int slot = c % NSTAGE;
        uint32_t ab = smem_base + slot * STAGE_BYTES;
        uint32_t bb = ab + A_SM_BYTES;
        #pragma unroll
        for (int i = 0; i < 4; i++) {
            int g = tid + i * 256;
            int r = g >> 3, gc = g & 7;
            CP_ASYNC16(ab + (uint32_t)(r * 144 + gc * 16),
                       aSrc + (size_t)r * (DIM * 4) + (size_t)c * (BK * 4) + gc * 16);
        }
        #pragma unroll
        for (int i = 0; i < 4; i++) {
            int g = tid + i * 256;
            int r = g >> 5, gc = g & 31;
            CP_ASYNC16(bb + (uint32_t)(r * 544 + gc * 16),
                       bSrc + (size_t)(c * BK + r) * (DIM * 4) + gc * 16);
        }
        asm volatile("cp.async.commit_group;" ::: "memory");
    };

    issue(0);
    issue(1);

    for (int c = 0; c < NCH; c++) {
        if (c < NCH - 1) asm volatile("cp.async.wait_group 1;" ::: "memory");
        else             asm volatile("cp.async.wait_group 0;" ::: "memory");
        __syncthreads();
        if (c + 2 < NCH) issue(c + 2);

        int slot = c % NSTAGE;
        const uint32_t* As = (const uint32_t*)(smem + slot * STAGE_BYTES);
        const uint32_t* Bs = (const uint32_t*)(smem + slot * STAGE_BYTES + A_SM_BYTES);

#pragma unroll
        for (int k8 = 0; k8 < BK; k8 += 8) {
            uint32_t af[4][4], bf[4][2];
#pragma unroll
            for (int i = 0; i < 4; i++) {
                int row = wm * 64 + i * 16 + gq;
                int col = k8 + tr;
                af[i][0] = As[row * 36 + col];
                af[i][1] = As[(row + 8) * 36 + col];
                af[i][2] = As[row * 36 + col + 4];
                af[i][3] = As[(row + 8) * 36 + col + 4];
            }
#pragma unroll
            for (int j = 0; j < 4; j++) {
                int coln = wn * 32 + j * 8 + gq;
                int rk = k8 + tr;
                bf[j][0] = Bs[rk * 136 + coln];
                bf[j][1] = Bs[(rk + 4) * 136 + coln];
            }
#pragma unroll
            for (int i = 0; i < 4; i++)
#pragma unroll
                for (int j = 0; j < 4; j++) {
                    asm volatile(
                        "mma.sync.aligned.m16n8k8.row.col.f32.tf32.tf32.f32 "
                        "{%0,%1,%2,%3}, {%4,%5,%6,%7}, {%8,%9}, {%0,%1,%2,%3};"
                        : "+f"(acc[i][j][0]), "+f"(acc[i][j][1]),
                          "+f"(acc[i][j][2]), "+f"(acc[i][j][3])
                        : "r"(af[i][0]), "r"(af[i][1]), "r"(af[i][2]), "r"(af[i][3]),
                          "r"(bf[j][0]), "r"(bf[j][1]));
                }
        }
        __syncthreads();
    }

    // ---- epilogue: bias + GELU; H (tf32-rounded) + routed output rows ----
    int hLim = g_lim[hLimSel];
    int rbase = bm * BM + wm * 64;
    int cbase = bn * BN + wn * 32;
#pragma unroll
    for (int i = 0; i < 4; i++) {
        int row0 = rbase + i * 16 + gq;
        int row1 = row0 + 8;
        int orig0 = compact ? g_perm[row0] : row0;
        int orig1 = compact ? g_perm[row1] : row1;
        int hdst0 = compact ? row0 : g_pos[row0];
        int hdst1 = compact ? row1 : g_pos[row1];
        int rt0 = g_route[orig0], rt1 = g_route[orig1];
#pragma unroll
        for (int j = 0; j < 4; j++) {
            int col = cbase + j * 8 + 2 * tr;
            float b0 = bias[col], b1 = bias[col + 1];
            float v00 = gelu_f(acc[i][j][0] + b0);
            float v01 = gelu_f(acc[i][j][1] + b1);
            float v10 = gelu_f(acc[i][j][2] + b0);
            float v11 = gelu_f(acc[i][j][3] + b1);
            if (Hptr) {
                if (hdst0 < hLim) {
                    float2 h0 = make_float2(__uint_as_float(f2tf32(v00)), __uint_as_float(f2tf32(v01)));
                    *(float2*)&Hptr[(size_t)hdst0 * DIM + col] = h0;
                }
                if (hdst1 < hLim) {
                    float2 h1 = make_float2(__uint_as_float(f2tf32(v10)), __uint_as_float(f2tf32(v11)));
                    *(float2*)&Hptr[(size_t)hdst1 * DIM + col] = h1;
                }
            }
            if (outp) {
                if (rt0 == outLevel) *(float2*)&outp[(size_t)orig0 * DIM + col] = make_float2(v00, v01);
                if (rt1 == outLevel) *(float2*)&outp[(size_t)orig1 * DIM + col] = make_float2(v10, v11);
            }
        }
    }
}

// ---------------------------------------------------------------------------
extern "C" void kernel_launch(void* const* d_in, const int* in_sizes, int n_in,
                              void* d_out, int out_size) {
    const float* x   = (const float*)d_in[0];
    const float* unc = (const float*)d_in[1];
    const float* Ws  = (const float*)d_in[2];
    const float* bs  = (const float*)d_in[3];
    const float* rw1 = (const float*)d_in[4];
    const float* rb1 = (const float*)d_in[5];
    const float* rw2 = (const float*)d_in[6];
    const float* rb2 = (const float*)d_in[7];
    const float* rw3 = (const float*)d_in[8];
    const float* rb3 = (const float*)d_in[9];

    float* out  = (float*)d_out;
    float* mask = out + (size_t)BROWS * DIM;

    cudaFuncSetAttribute(gemm_kernel, cudaFuncAttributeMaxDynamicSharedMemorySize, SMEM_TOTAL);

    // launch order keeps L0 GEMM at ncu's captured slot (index 3)
    route_fused_kernel<<<1, 1024>>>(unc, rw1, rb1, rw2, rb2, rw3, rb3, mask);
    convx_kernel<<<(BROWS * (DIM / 4)) / 256, 256>>>(x);
    convw_kernel<<<(4 * DIM * (DIM / 4)) / 256, 256>>>(Ws);

    dim3 grid(DIM / BN, BROWS / BM);  // (16, 64); CTAs beyond g_lim early-exit
    // L0: A=g_X (orig), H0 scattered to compact order; route==0 rows -> out
    gemm_kernel<<<grid, 256, SMEM_TOTAL>>>(bs, out,     0, 0, 1, 0,  0, 0, 1);
    // L1: A=H0 compact prefix ceil128(n1+n2); H1 (prefix n2r); route==1 -> out
    gemm_kernel<<<grid, 256, SMEM_TOTAL>>>(bs, out,     1, 1, 2, 1,  1, 1, 2);
    // L2: A=H1 compact prefix ceil128(n2); H2
    gemm_kernel<<<grid, 256, SMEM_TOTAL>>>(bs, nullptr, 2, 2, 3, -1, 1, 2, 2);
    // L3: A=H2 compact prefix ceil128(n2); route==2 -> out
    gemm_kernel<<<grid, 256, SMEM_TOTAL>>>(bs, out,     3, 3, 0, 2,  1, 2, 0);
}

// round 7
// speedup vs baseline: 1.1314x; 1.0253x over previous
#include <cuda_runtime.h>
#include <cstdint>
#include <cfloat>

#define BROWS 8192
#define DIM   2048
#define NBLK  (BROWS/128)

#define BM 128
#define BN 128
#define BK 32
#define NCH (DIM/BK)              // 64 k-iterations
// both tiles [128 rows][36 words] — 144B stride, LDSM conflict-free
#define T_SM_WORDS 36
#define T_SM_BYTES (128*T_SM_WORDS*4)   // 18432
#define A_SM_BYTES T_SM_BYTES
#define STAGE_BYTES (2*T_SM_BYTES)      // 36864
#define NSTAGE 3
#define SMEM_TOTAL (NSTAGE*STAGE_BYTES) // 110592

#define NTHREADS 128              // 4 warps, 2x2 grid of 64x64 warp tiles

// ------------------------- persistent device scratch -------------------------
__device__ __align__(16) float g_X [(size_t)BROWS * DIM];      // tf32-rounded x
__device__ __align__(16) float g_Wt[(size_t)4 * DIM * DIM];    // tf32-rounded W^T: [l][n][k]
__device__ __align__(16) float g_H0[(size_t)BROWS * DIM];
__device__ __align__(16) float g_H1[(size_t)BROWS * DIM];
__device__ __align__(16) float g_H2[(size_t)BROWS * DIM];
__device__ int g_route[BROWS];
__device__ int g_need1[NBLK];
__device__ int g_need2[NBLK];

// ------------------------------- helpers --------------------------------
__device__ __forceinline__ uint32_t smem_u32(const void* p) {
    uint32_t a;
    asm("{ .reg .u64 t; cvta.to.shared.u64 t, %1; cvt.u32.u64 %0, t; }" : "=r"(a) : "l"(p));
    return a;
}
__device__ __forceinline__ uint32_t f2tf32(float x) {
    uint32_t y; asm("cvt.rna.tf32.f32 %0, %1;" : "=r"(y) : "f"(x)); return y;
}
#define CP_ASYNC16(dst, src) \
    asm volatile("cp.async.cg.shared.global [%0], [%1], 16;" :: "r"(dst), "l"(src) : "memory")
#define LDSM_X4(r0, r1, r2, r3, addr) \
    asm volatile("ldmatrix.sync.aligned.m8n8.x4.shared.b16 {%0,%1,%2,%3}, [%4];" \
                 : "=r"(r0), "=r"(r1), "=r"(r2), "=r"(r3) : "r"(addr))

__device__ __forceinline__ float gelu_f(float x) {
    float x3 = x * x * x;
    float t = tanhf(0.7978845608028654f * (x + 0.044715f * x3));
    return 0.5f * x * (1.f + t);
}

// ---------------------------------------------------------------------------
// Fused: min/max + router MLP + tile flags. One block, 1024 threads.
// ---------------------------------------------------------------------------
__global__ __launch_bounds__(1024)
void route_fused_kernel(const float* __restrict__ unc,
                        const float* __restrict__ rw1, const float* __restrict__ rb1,
                        const float* __restrict__ rw2, const float* __restrict__ rb2,
                        const float* __restrict__ rw3, const float* __restrict__ rb3,
                        float* __restrict__ out_mask) {
    __shared__ float smin[1024], smax[1024];
    __shared__ float s_w1[32], s_b1[32], s_w2[512], s_b2[16], s_w3[48], s_b3[3];
    __shared__ float s_mn, s_mx;
    int t = threadIdx.x;

    if (t < 32) { s_w1[t] = rw1[t]; s_b1[t] = rb1[t]; }
    if (t >= 256 && t < 768) s_w2[t - 256] = rw2[t - 256];
    if (t >= 768 && t < 784) s_b2[t - 768] = rb2[t - 768];
    if (t >= 800 && t < 848) s_w3[t - 800] = rw3[t - 800];
    if (t >= 864 && t < 867) s_b3[t - 864] = rb3[t - 864];
    if (t < NBLK) { g_need1[t] = 0; g_need2[t] = 0; }

    float mn = FLT_MAX, mx = -FLT_MAX;
    for (int i = t; i < BROWS; i += 1024) {
        float v = unc[i];
        mn = fminf(mn, v); mx = fmaxf(mx, v);
    }
    smin[t] = mn; smax[t] = mx;
    __syncthreads();
    for (int s = 512; s > 0; s >>= 1) {
        if (t < s) {
            smin[t] = fminf(smin[t], smin[t + s]);
            smax[t] = fmaxf(smax[t], smax[t + s]);
        }
        __syncthreads();
    }
    if (t == 0) { s_mn = smin[0]; s_mx = smax[0]; }
    __syncthreads();

    float vmn = s_mn, vmx = s_mx;
    for (int i = t; i < BROWS; i += 1024) {
        float u = (unc[i] - vmn) / (vmx - vmn + 1e-8f);
        float h1[32];
#pragma unroll
        for (int j = 0; j < 32; j++) h1[j] = fmaxf(fmaf(u, s_w1[j], s_b1[j]), 0.f);
        float h2[16];
#pragma unroll
        for (int j = 0; j < 16; j++) {
            float a = s_b2[j];
#pragma unroll
            for (int k = 0; k < 32; k++) a = fmaf(h1[k], s_w2[k * 16 + j], a);
            h2[j] = fmaxf(a, 0.f);
        }
        float l[3];
#pragma unroll
        for (int j = 0; j < 3; j++) {
            float a = s_b3[j];
#pragma unroll
            for (int k = 0; k < 16; k++) a = fmaf(h2[k], s_w3[k * 3 + j], a);
            l[j] = a;
        }
        int r = 0; float best = l[0];
        if (l[1] > best) { best = l[1]; r = 1; }
        if (l[2] > best) { best = l[2]; r = 2; }
        g_route[i]  = r;
        out_mask[i] = (float)r;
        if (r >= 1) atomicOr(&g_need1[i >> 7], 1);
        if (r == 2) atomicOr(&g_need2[i >> 7], 1);
    }
}

// ---------------------------------------------------------------------------
// prep: x -> g_X (tf32);  W[l][k][n] -> g_Wt[l][n][k] (tf32)
// ---------------------------------------------------------------------------
__global__ void convx_kernel(const float* __restrict__ x) {
    size_t i = ((size_t)blockIdx.x * 256 + threadIdx.x) * 4;
    float4 v = *(const float4*)(x + i);
    v.x = __uint_as_float(f2tf32(v.x)); v.y = __uint_as_float(f2tf32(v.y));
    v.z = __uint_as_float(f2tf32(v.z)); v.w = __uint_as_float(f2tf32(v.w));
    *(float4*)(g_X + i) = v;
}
__global__ void transW_kernel(const float* __restrict__ Ws) {
    __shared__ float tile[32][33];
    int l = blockIdx.z;
    int n0 = blockIdx.x * 32, k0 = blockIdx.y * 32;
    const float* Wl = Ws + (size_t)l * DIM * DIM;
#pragma unroll
    for (int i = 0; i < 4; i++)
        tile[threadIdx.y + i * 8][threadIdx.x] =
            Wl[(size_t)(k0 + threadIdx.y + i * 8) * DIM + n0 + threadIdx.x];
    __syncthreads();
    float* Wt = g_Wt + (size_t)l * DIM * DIM;
#pragma unroll
    for (int i = 0; i < 4; i++) {
        int n = n0 + threadIdx.y + i * 8;
        Wt[(size_t)n * DIM + k0 + threadIdx.x] =
            __uint_as_float(f2tf32(tile[threadIdx.x][threadIdx.y + i * 8]));
    }
}

// ---------------------------------------------------------------------------
// TF32 mma.sync GEMM, 3-stage cp.async, ldmatrix fragments.
// CTA 128x128x32, 128 threads (4 warps 2x2), warp tile 64x64, m16n8k8.
// B operand from g_Wt ([n][k]) so both tiles are K-major in smem.
// ---------------------------------------------------------------------------
__global__ __launch_bounds__(NTHREADS, 2)
void gemm_kernel(const float* __restrict__ ball, float* __restrict__ outp,
                 int layerIdx, int abuf, int hbuf, int outLevel, int needSel) {
    int bn = blockIdx.x, bm = blockIdx.y;
    if (needSel == 1 && !g_need1[bm]) return;
    if (needSel == 2 && !g_need2[bm]) return;

    extern __shared__ char smem[];
    uint32_t smem_base = smem_u32(smem);

    const float* A = (abuf == 0) ? g_X : (abuf == 1 ? g_H0 : (abuf == 2 ? g_H1 : g_H2));
    float* Hptr = (hbuf == 1) ? g_H0 : (hbuf == 2 ? g_H1 : (hbuf == 3 ? g_H2 : nullptr));
    const float* bias = ball + layerIdx * DIM;
    const char* aSrc = (const char*)(A + (size_t)bm * BM * DIM);
    const char* bSrc = (const char*)(g_Wt + (size_t)layerIdx * DIM * DIM + (size_t)bn * BN * DIM);

    int tid  = threadIdx.x;
    int warp = tid >> 5, lane = tid & 31;
    int wm = warp >> 1, wn = warp & 1;     // 2x2 warp grid, 64x64 per warp
    int gq = lane >> 2, tr = lane & 3;

    // ldmatrix per-lane addressing (matrix index m = lane>>3)
    int a_row = ((lane >> 3) & 1) * 8 + (lane & 7);   // (m&1)*8 + row-in-matrix
    int a_colB = (lane >> 4) * 16;                    // (m>>1)*4 tf32 = 16B
    int b_row = (lane >> 4) * 8 + (lane & 7);         // (m>>1)*8 + row
    int b_colB = ((lane >> 3) & 1) * 16;              // (m&1)*4 tf32 = 16B

    float acc[4][8][4];
#pragma unroll
    for (int i = 0; i < 4; i++)
#pragma unroll
        for (int j = 0; j < 8; j++)
#pragma unroll
            for (int r = 0; r < 4; r++) acc[i][j][r] = 0.f;

    // --- async load issuer: 16 x 16B cp.async per thread per stage ---
    auto issue = [&](int c) {
        int slot = c % NSTAGE;
        uint32_t ab = smem_base + slot * STAGE_BYTES;
        uint32_t bb = ab + A_SM_BYTES;
        #pragma unroll
        for (int i = 0; i < 8; i++) {
            int g = tid + i * NTHREADS;
            int r = g >> 3, gc = g & 7;
            CP_ASYNC16(ab + (uint32_t)(r * 144 + gc * 16),
                       aSrc + (size_t)r * (DIM * 4) + (size_t)c * (BK * 4) + gc * 16);
        }
        #pragma unroll
        for (int i = 0; i < 8; i++) {
            int g = tid + i * NTHREADS;
            int r = g >> 3, gc = g & 7;
            CP_ASYNC16(bb + (uint32_t)(r * 144 + gc * 16),
                       bSrc + (size_t)r * (DIM * 4) + (size_t)c * (BK * 4) + gc * 16);
        }
        asm volatile("cp.async.commit_group;" ::: "memory");
    };

    issue(0);
    issue(1);

    for (int c = 0; c < NCH; c++) {
        if (c < NCH - 1) asm volatile("cp.async.wait_group 1;" ::: "memory");
        else             asm volatile("cp.async.wait_group 0;" ::: "memory");
        __syncthreads();
        if (c + 2 < NCH) issue(c + 2);

        int slot = c % NSTAGE;
        uint32_t aBase = smem_base + slot * STAGE_BYTES
                       + (uint32_t)((wm * 64 + a_row) * 144 + a_colB);
        uint32_t bBase = smem_base + slot * STAGE_BYTES + A_SM_BYTES
                       + (uint32_t)((wn * 64 + b_row) * 144 + b_colB);

#pragma unroll
        for (int k8 = 0; k8 < BK; k8 += 8) {
            uint32_t af[4][4], bf[8][2];
#pragma unroll
            for (int i = 0; i < 4; i++)
                LDSM_X4(af[i][0], af[i][1], af[i][2], af[i][3],
                        aBase + (uint32_t)(i * 16 * 144 + k8 * 4));
#pragma unroll
            for (int jp = 0; jp < 4; jp++)
                LDSM_X4(bf[2 * jp][0], bf[2 * jp][1], bf[2 * jp + 1][0], bf[2 * jp + 1][1],
                        bBase + (uint32_t)(jp * 16 * 144 + k8 * 4));
#pragma unroll
            for (int i = 0; i < 4; i++)
#pragma unroll
                for (int j = 0; j < 8; j++) {
                    asm volatile(
                        "mma.sync.aligned.m16n8k8.row.col.f32.tf32.tf32.f32 "
                        "{%0,%1,%2,%3}, {%4,%5,%6,%7}, {%8,%9}, {%0,%1,%2,%3};"
                        : "+f"(acc[i][j][0]), "+f"(acc[i][j][1]),
                          "+f"(acc[i][j][2]), "+f"(acc[i][j][3])
                        : "r"(af[i][0]), "r"(af[i][1]), "r"(af[i][2]), "r"(af[i][3]),
                          "r"(bf[j][0]), "r"(bf[j][1]));
                }
        }
        __syncthreads();
    }

    // ---- epilogue: bias + GELU; H stored tf32-rounded, routed rows -> out ----
    int rbase = bm * BM + wm * 64;
    int cbase = bn * BN + wn * 64;
#pragma unroll
    for (int i = 0; i < 4; i++) {
        int row0 = rbase + i * 16 + gq;
        int row1 = row0 + 8;
        int rt0 = g_route[row0], rt1 = g_route[row1];
#pragma unroll
        for (int j = 0; j < 8; j++) {
            int col = cbase + j * 8 + 2 * tr;
            float b0 = bias[col], b1 = bias[col + 1];
            float v00 = gelu_f(acc[i][j][0] + b0);
            float v01 = gelu_f(acc[i][j][1] + b1);
            float v10 = gelu_f(acc[i][j][2] + b0);
            float v11 = gelu_f(acc[i][j][3] + b1);
            if (Hptr) {
                float2 h0 = make_float2(__uint_as_float(f2tf32(v00)), __uint_as_float(f2tf32(v01)));
                float2 h1 = make_float2(__uint_as_float(f2tf32(v10)), __uint_as_float(f2tf32(v11)));
                *(float2*)&Hptr[(size_t)row0 * DIM + col] = h0;
                *(float2*)&Hptr[(size_t)row1 * DIM + col] = h1;
            }
            if (outp) {
                if (rt0 == outLevel) *(float2*)&outp[(size_t)row0 * DIM + col] = make_float2(v00, v01);
                if (rt1 == outLevel) *(float2*)&outp[(size_t)row1 * DIM + col] = make_float2(v10, v11);
            }
        }
    }
}

// ---------------------------------------------------------------------------
extern "C" void kernel_launch(void* const* d_in, const int* in_sizes, int n_in,
                              void* d_out, int out_size) {
    const float* x   = (const float*)d_in[0];
    const float* unc = (const float*)d_in[1];
    const float* Ws  = (const float*)d_in[2];
    const float* bs  = (const float*)d_in[3];
    const float* rw1 = (const float*)d_in[4];
    const float* rb1 = (const float*)d_in[5];
    const float* rw2 = (const float*)d_in[6];
    const float* rb2 = (const float*)d_in[7];
    const float* rw3 = (const float*)d_in[8];
    const float* rb3 = (const float*)d_in[9];

    float* out  = (float*)d_out;
    float* mask = out + (size_t)BROWS * DIM;

    cudaFuncSetAttribute(gemm_kernel, cudaFuncAttributeMaxDynamicSharedMemorySize, SMEM_TOTAL);

    // launch order keeps L0 GEMM at ncu's captured slot (index 3)
    route_fused_kernel<<<1, 1024>>>(unc, rw1, rb1, rw2, rb2, rw3, rb3, mask);
    convx_kernel<<<(BROWS * (DIM / 4)) / 256, 256>>>(x);
    transW_kernel<<<dim3(64, 64, 4), dim3(32, 8)>>>(Ws);

    dim3 grid(DIM / BN, BROWS / BM);  // (16, 64)
    // L0: in=g_X, H=g_H0, rows route==0 -> out
    gemm_kernel<<<grid, NTHREADS, SMEM_TOTAL>>>(bs, out,     0, 0, 1, 0,  0);
    // L1: in=H0, H=H1, rows route==1 -> out ; skip tiles with no route>=1
    gemm_kernel<<<grid, NTHREADS, SMEM_TOTAL>>>(bs, out,     1, 1, 2, 1,  1);
    // L2: in=H1, H=H2 ; skip tiles with no route==2
    gemm_kernel<<<grid, NTHREADS, SMEM_TOTAL>>>(bs, nullptr, 2, 2, 3, -1, 2);
    // L3: in=H2, rows route==2 -> out ; skip tiles with no route==2
    gemm_kernel<<<grid, NTHREADS, SMEM_TOTAL>>>(bs, out,     3, 3, 0, 2,  2);
}

// round 8
// speedup vs baseline: 1.1838x; 1.0463x over previous
#include <cuda_runtime.h>
#include <cstdint>
#include <cfloat>

#define BROWS 8192
#define DIM   2048
#define NBLK  (BROWS/128)

#define BM 128
#define BN 128
#define BK 32
#define NCH (DIM/BK)              // 64 k-iterations
// both tiles [128 rows][36 words] — 144B stride, LDSM conflict-free
#define T_SM_WORDS 36
#define T_SM_BYTES (128*T_SM_WORDS*4)   // 18432
#define A_SM_BYTES T_SM_BYTES
#define STAGE_BYTES (2*T_SM_BYTES)      // 36864
#define NSTAGE 3
#define SMEM_TOTAL (NSTAGE*STAGE_BYTES) // 110592

#define NTHREADS 256              // 8 warps, 2x4 grid of 64x32 warp tiles

// ------------------------- persistent device scratch -------------------------
__device__ __align__(16) float g_X [(size_t)BROWS * DIM];      // tf32-rounded x
__device__ __align__(16) float g_Wt[(size_t)4 * DIM * DIM];    // tf32-rounded W^T: [l][n][k]
__device__ __align__(16) float g_H0[(size_t)BROWS * DIM];
__device__ __align__(16) float g_H1[(size_t)BROWS * DIM];
__device__ __align__(16) float g_H2[(size_t)BROWS * DIM];
__device__ int g_route[BROWS];
__device__ int g_need1[NBLK];
__device__ int g_need2[NBLK];

// ------------------------------- helpers --------------------------------
__device__ __forceinline__ uint32_t smem_u32(const void* p) {
    uint32_t a;
    asm("{ .reg .u64 t; cvta.to.shared.u64 t, %1; cvt.u32.u64 %0, t; }" : "=r"(a) : "l"(p));
    return a;
}
__device__ __forceinline__ uint32_t f2tf32(float x) {
    uint32_t y; asm("cvt.rna.tf32.f32 %0, %1;" : "=r"(y) : "f"(x)); return y;
}
#define CP_ASYNC16(dst, src) \
    asm volatile("cp.async.cg.shared.global [%0], [%1], 16;" :: "r"(dst), "l"(src) : "memory")
#define LDSM_X4(r0, r1, r2, r3, addr) \
    asm volatile("ldmatrix.sync.aligned.m8n8.x4.shared.b16 {%0,%1,%2,%3}, [%4];" \
                 : "=r"(r0), "=r"(r1), "=r"(r2), "=r"(r3) : "r"(addr))

__device__ __forceinline__ float gelu_f(float x) {
    float x3 = x * x * x;
    float t = tanhf(0.7978845608028654f * (x + 0.044715f * x3));
    return 0.5f * x * (1.f + t);
}

// ---------------------------------------------------------------------------
// Fused: min/max + router MLP + tile flags. One block, 1024 threads.
// ---------------------------------------------------------------------------
__global__ __launch_bounds__(1024)
void route_fused_kernel(const float* __restrict__ unc,
                        const float* __restrict__ rw1, const float* __restrict__ rb1,
                        const float* __restrict__ rw2, const float* __restrict__ rb2,
                        const float* __restrict__ rw3, const float* __restrict__ rb3,
                        float* __restrict__ out_mask) {
    __shared__ float smin[1024], smax[1024];
    __shared__ float s_w1[32], s_b1[32], s_w2[512], s_b2[16], s_w3[48], s_b3[3];
    __shared__ float s_mn, s_mx;
    int t = threadIdx.x;

    if (t < 32) { s_w1[t] = rw1[t]; s_b1[t] = rb1[t]; }
    if (t >= 256 && t < 768) s_w2[t - 256] = rw2[t - 256];
    if (t >= 768 && t < 784) s_b2[t - 768] = rb2[t - 768];
    if (t >= 800 && t < 848) s_w3[t - 800] = rw3[t - 800];
    if (t >= 864 && t < 867) s_b3[t - 864] = rb3[t - 864];
    if (t < NBLK) { g_need1[t] = 0; g_need2[t] = 0; }

    float mn = FLT_MAX, mx = -FLT_MAX;
    for (int i = t; i < BROWS; i += 1024) {
        float v = unc[i];
        mn = fminf(mn, v); mx = fmaxf(mx, v);
    }
    smin[t] = mn; smax[t] = mx;
    __syncthreads();
    for (int s = 512; s > 0; s >>= 1) {
        if (t < s) {
            smin[t] = fminf(smin[t], smin[t + s]);
            smax[t] = fmaxf(smax[t], smax[t + s]);
        }
        __syncthreads();
    }
    if (t == 0) { s_mn = smin[0]; s_mx = smax[0]; }
    __syncthreads();

    float vmn = s_mn, vmx = s_mx;
    for (int i = t; i < BROWS; i += 1024) {
        float u = (unc[i] - vmn) / (vmx - vmn + 1e-8f);
        float h1[32];
#pragma unroll
        for (int j = 0; j < 32; j++) h1[j] = fmaxf(fmaf(u, s_w1[j], s_b1[j]), 0.f);
        float h2[16];
#pragma unroll
        for (int j = 0; j < 16; j++) {
            float a = s_b2[j];
#pragma unroll
            for (int k = 0; k < 32; k++) a = fmaf(h1[k], s_w2[k * 16 + j], a);
            h2[j] = fmaxf(a, 0.f);
        }
        float l[3];
#pragma unroll
        for (int j = 0; j < 3; j++) {
            float a = s_b3[j];
#pragma unroll
            for (int k = 0; k < 16; k++) a = fmaf(h2[k], s_w3[k * 3 + j], a);
            l[j] = a;
        }
        int r = 0; float best = l[0];
        if (l[1] > best) { best = l[1]; r = 1; }
        if (l[2] > best) { best = l[2]; r = 2; }
        g_route[i]  = r;
        out_mask[i] = (float)r;
        if (r >= 1) atomicOr(&g_need1[i >> 7], 1);
        if (r == 2) atomicOr(&g_need2[i >> 7], 1);
    }
}

// ---------------------------------------------------------------------------
// prep: x -> g_X (tf32);  W[l][k][n] -> g_Wt[l][n][k] (tf32)
// ---------------------------------------------------------------------------
__global__ void convx_kernel(const float* __restrict__ x) {
    size_t i = ((size_t)blockIdx.x * 256 + threadIdx.x) * 4;
    float4 v = *(const float4*)(x + i);
    v.x = __uint_as_float(f2tf32(v.x)); v.y = __uint_as_float(f2tf32(v.y));
    v.z = __uint_as_float(f2tf32(v.z)); v.w = __uint_as_float(f2tf32(v.w));
    *(float4*)(g_X + i) = v;
}
__global__ void transW_kernel(const float* __restrict__ Ws) {
    __shared__ float tile[32][33];
    int l = blockIdx.z;
    int n0 = blockIdx.x * 32, k0 = blockIdx.y * 32;
    const float* Wl = Ws + (size_t)l * DIM * DIM;
#pragma unroll
    for (int i = 0; i < 4; i++)
        tile[threadIdx.y + i * 8][threadIdx.x] =
            Wl[(size_t)(k0 + threadIdx.y + i * 8) * DIM + n0 + threadIdx.x];
    __syncthreads();
    float* Wt = g_Wt + (size_t)l * DIM * DIM;
#pragma unroll
    for (int i = 0; i < 4; i++) {
        int n = n0 + threadIdx.y + i * 8;
        Wt[(size_t)n * DIM + k0 + threadIdx.x] =
            __uint_as_float(f2tf32(tile[threadIdx.x][threadIdx.y + i * 8]));
    }
}

// ---------------------------------------------------------------------------
// TF32 mma.sync GEMM, 3-stage cp.async, ldmatrix fragments.
// CTA 128x128x32, 256 threads (8 warps 2x4), warp tile 64x32, m16n8k8.
// 4 warps per SMSP hide LDSM latency; 2 CTAs/SM.
// ---------------------------------------------------------------------------
__global__ __launch_bounds__(NTHREADS, 2)
void gemm_kernel(const float* __restrict__ ball, float* __restrict__ outp,
                 int layerIdx, int abuf, int hbuf, int outLevel, int needSel) {
    int bn = blockIdx.x, bm = blockIdx.y;
    if (needSel == 1 && !g_need1[bm]) return;
    if (needSel == 2 && !g_need2[bm]) return;

    extern __shared__ char smem[];
    uint32_t smem_base = smem_u32(smem);

    const float* A = (abuf == 0) ? g_X : (abuf == 1 ? g_H0 : (abuf == 2 ? g_H1 : g_H2));
    float* Hptr = (hbuf == 1) ? g_H0 : (hbuf == 2 ? g_H1 : (hbuf == 3 ? g_H2 : nullptr));
    const float* bias = ball + layerIdx * DIM;
    const char* aSrc = (const char*)(A + (size_t)bm * BM * DIM);
    const char* bSrc = (const char*)(g_Wt + (size_t)layerIdx * DIM * DIM + (size_t)bn * BN * DIM);

    int tid  = threadIdx.x;
    int warp = tid >> 5, lane = tid & 31;
    int wm = warp >> 2, wn = warp & 3;     // 2x4 warp grid, 64x32 per warp
    int gq = lane >> 2, tr = lane & 3;

    // ldmatrix per-lane addressing (matrix index m = lane>>3)
    int a_row = ((lane >> 3) & 1) * 8 + (lane & 7);   // (m&1)*8 + row-in-matrix
    int a_colB = (lane >> 4) * 16;                    // (m>>1)*4 tf32 = 16B
    int b_row = (lane >> 4) * 8 + (lane & 7);         // (m>>1)*8 + row
    int b_colB = ((lane >> 3) & 1) * 16;              // (m&1)*4 tf32 = 16B

    float acc[4][4][4];
#pragma unroll
    for (int i = 0; i < 4; i++)
#pragma unroll
        for (int j = 0; j < 4; j++)
#pragma unroll
            for (int r = 0; r < 4; r++) acc[i][j][r] = 0.f;

    // --- async load issuer: 8 x 16B cp.async per thread per stage ---
    auto issue = [&](int c) {
        int slot = c % NSTAGE;
        uint32_t ab = smem_base + slot * STAGE_BYTES;
        uint32_t bb = ab + A_SM_BYTES;
        #pragma unroll
        for (int i = 0; i < 4; i++) {
            int g = tid + i * NTHREADS;
            int r = g >> 3, gc = g & 7;
            CP_ASYNC16(ab + (uint32_t)(r * 144 + gc * 16),
                       aSrc + (size_t)r * (DIM * 4) + (size_t)c * (BK * 4) + gc * 16);
        }
        #pragma unroll
        for (int i = 0; i < 4; i++) {
            int g = tid + i * NTHREADS;
            int r = g >> 3, gc = g & 7;
            CP_ASYNC16(bb + (uint32_t)(r * 144 + gc * 16),
                       bSrc + (size_t)r * (DIM * 4) + (size_t)c * (BK * 4) + gc * 16);
        }
        asm volatile("cp.async.commit_group;" ::: "memory");
    };

    issue(0);
    issue(1);

    for (int c = 0; c < NCH; c++) {
        if (c < NCH - 1) asm volatile("cp.async.wait_group 1;" ::: "memory");
        else             asm volatile("cp.async.wait_group 0;" ::: "memory");
        __syncthreads();
        if (c + 2 < NCH) issue(c + 2);

        int slot = c % NSTAGE;
        uint32_t aBase = smem_base + slot * STAGE_BYTES
                       + (uint32_t)((wm * 64 + a_row) * 144 + a_colB);
        uint32_t bBase = smem_base + slot * STAGE_BYTES + A_SM_BYTES
                       + (uint32_t)((wn * 32 + b_row) * 144 + b_colB);

#pragma unroll
        for (int k8 = 0; k8 < BK; k8 += 8) {
            uint32_t af[4][4], bf[4][2];
#pragma unroll
            for (int i = 0; i < 4; i++)
                LDSM_X4(af[i][0], af[i][1], af[i][2], af[i][3],
                        aBase + (uint32_t)(i * 16 * 144 + k8 * 4));
#pragma unroll
            for (int jp = 0; jp < 2; jp++)
                LDSM_X4(bf[2 * jp][0], bf[2 * jp][1], bf[2 * jp + 1][0], bf[2 * jp + 1][1],
                        bBase + (uint32_t)(jp * 16 * 144 + k8 * 4));
#pragma unroll
            for (int i = 0; i < 4; i++)
#pragma unroll
                for (int j = 0; j < 4; j++) {
                    asm volatile(
                        "mma.sync.aligned.m16n8k8.row.col.f32.tf32.tf32.f32 "
                        "{%0,%1,%2,%3}, {%4,%5,%6,%7}, {%8,%9}, {%0,%1,%2,%3};"
                        : "+f"(acc[i][j][0]), "+f"(acc[i][j][1]),
                          "+f"(acc[i][j][2]), "+f"(acc[i][j][3])
                        : "r"(af[i][0]), "r"(af[i][1]), "r"(af[i][2]), "r"(af[i][3]),
                          "r"(bf[j][0]), "r"(bf[j][1]));
                }
        }
        __syncthreads();
    }

    // ---- epilogue: bias + GELU; H stored tf32-rounded, routed rows -> out ----
    int rbase = bm * BM + wm * 64;
    int cbase = bn * BN + wn * 32;
#pragma unroll
    for (int i = 0; i < 4; i++) {
        int row0 = rbase + i * 16 + gq;
        int row1 = row0 + 8;
        int rt0 = g_route[row0], rt1 = g_route[row1];
#pragma unroll
        for (int j = 0; j < 4; j++) {
            int col = cbase + j * 8 + 2 * tr;
            float b0 = bias[col], b1 = bias[col + 1];
            float v00 = gelu_f(acc[i][j][0] + b0);
            float v01 = gelu_f(acc[i][j][1] + b1);
            float v10 = gelu_f(acc[i][j][2] + b0);
            float v11 = gelu_f(acc[i][j][3] + b1);
            if (Hptr) {
                float2 h0 = make_float2(__uint_as_float(f2tf32(v00)), __uint_as_float(f2tf32(v01)));
                float2 h1 = make_float2(__uint_as_float(f2tf32(v10)), __uint_as_float(f2tf32(v11)));
                *(float2*)&Hptr[(size_t)row0 * DIM + col] = h0;
                *(float2*)&Hptr[(size_t)row1 * DIM + col] = h1;
            }
            if (outp) {
                if (rt0 == outLevel) *(float2*)&outp[(size_t)row0 * DIM + col] = make_float2(v00, v01);
                if (rt1 == outLevel) *(float2*)&outp[(size_t)row1 * DIM + col] = make_float2(v10, v11);
            }
        }
    }
}

// ---------------------------------------------------------------------------
extern "C" void kernel_launch(void* const* d_in, const int* in_sizes, int n_in,
                              void* d_out, int out_size) {
    const float* x   = (const float*)d_in[0];
    const float* unc = (const float*)d_in[1];
    const float* Ws  = (const float*)d_in[2];
    const float* bs  = (const float*)d_in[3];
    const float* rw1 = (const float*)d_in[4];
    const float* rb1 = (const float*)d_in[5];
    const float* rw2 = (const float*)d_in[6];
    const float* rb2 = (const float*)d_in[7];
    const float* rw3 = (const float*)d_in[8];
    const float* rb3 = (const float*)d_in[9];

    float* out  = (float*)d_out;
    float* mask = out + (size_t)BROWS * DIM;

    cudaFuncSetAttribute(gemm_kernel, cudaFuncAttributeMaxDynamicSharedMemorySize, SMEM_TOTAL);

    // launch order keeps L0 GEMM at ncu's captured slot (index 3)
    route_fused_kernel<<<1, 1024>>>(unc, rw1, rb1, rw2, rb2, rw3, rb3, mask);
    convx_kernel<<<(BROWS * (DIM / 4)) / 256, 256>>>(x);
    transW_kernel<<<dim3(64, 64, 4), dim3(32, 8)>>>(Ws);

    dim3 grid(DIM / BN, BROWS / BM);  // (16, 64)
    // L0: in=g_X, H=g_H0, rows route==0 -> out
    gemm_kernel<<<grid, NTHREADS, SMEM_TOTAL>>>(bs, out,     0, 0, 1, 0,  0);
    // L1: in=H0, H=H1, rows route==1 -> out ; skip tiles with no route>=1
    gemm_kernel<<<grid, NTHREADS, SMEM_TOTAL>>>(bs, out,     1, 1, 2, 1,  1);
    // L2: in=H1, H=H2 ; skip tiles with no route==2
    gemm_kernel<<<grid, NTHREADS, SMEM_TOTAL>>>(bs, nullptr, 2, 2, 3, -1, 2);
    // L3: in=H2, rows route==2 -> out ; skip tiles with no route==2
    gemm_kernel<<<grid, NTHREADS, SMEM_TOTAL>>>(bs, out,     3, 3, 0, 2,  2);
}

// round 9
// speedup vs baseline: 1.8620x; 1.5728x over previous
#include <cuda_runtime.h>
#include <cuda_fp16.h>
#include <cstdint>
#include <cfloat>

#define BROWS 8192
#define DIM   2048
#define NBLK  (BROWS/128)

#define BM 128
#define BN 128
#define BK 32
#define NCH (DIM/BK)              // 64 k-iterations
// fp16 tiles: 128 rows x 32 fp16 (64B) padded to 80B stride — LDSM conflict-free
#define T_STRIDE 80
#define T_SM_BYTES (128*T_STRIDE)       // 10240
#define A_SM_BYTES T_SM_BYTES
#define STAGE_BYTES (2*T_SM_BYTES)      // 20480
#define NSTAGE 4
#define SMEM_TOTAL (NSTAGE*STAGE_BYTES) // 81920

#define NTHREADS 256              // 8 warps, 2x4 grid of 64x32 warp tiles

// ------------------------- persistent device scratch -------------------------
__device__ __align__(16) __half g_X [(size_t)BROWS * DIM];     // fp16 x
__device__ __align__(16) __half g_Wt[(size_t)4 * DIM * DIM];   // fp16 W^T: [l][n][k]
__device__ __align__(16) __half g_H0[(size_t)BROWS * DIM];
__device__ __align__(16) __half g_H1[(size_t)BROWS * DIM];
__device__ __align__(16) __half g_H2[(size_t)BROWS * DIM];
__device__ int g_route[BROWS];
__device__ int g_need1[NBLK];
__device__ int g_need2[NBLK];

// ------------------------------- helpers --------------------------------
__device__ __forceinline__ uint32_t smem_u32(const void* p) {
    uint32_t a;
    asm("{ .reg .u64 t; cvta.to.shared.u64 t, %1; cvt.u32.u64 %0, t; }" : "=r"(a) : "l"(p));
    return a;
}
#define CP_ASYNC16(dst, src) \
    asm volatile("cp.async.cg.shared.global [%0], [%1], 16;" :: "r"(dst), "l"(src) : "memory")
#define LDSM_X4(r0, r1, r2, r3, addr) \
    asm volatile("ldmatrix.sync.aligned.m8n8.x4.shared.b16 {%0,%1,%2,%3}, [%4];" \
                 : "=r"(r0), "=r"(r1), "=r"(r2), "=r"(r3) : "r"(addr))

__device__ __forceinline__ float gelu_f(float x) {
    float x3 = x * x * x;
    float t = tanhf(0.7978845608028654f * (x + 0.044715f * x3));
    return 0.5f * x * (1.f + t);
}

// ---------------------------------------------------------------------------
// Fused: min/max + router MLP + tile flags. One block, 1024 threads.
// ---------------------------------------------------------------------------
__global__ __launch_bounds__(1024)
void route_fused_kernel(const float* __restrict__ unc,
                        const float* __restrict__ rw1, const float* __restrict__ rb1,
                        const float* __restrict__ rw2, const float* __restrict__ rb2,
                        const float* __restrict__ rw3, const float* __restrict__ rb3,
                        float* __restrict__ out_mask) {
    __shared__ float smin[1024], smax[1024];
    __shared__ float s_w1[32], s_b1[32], s_w2[512], s_b2[16], s_w3[48], s_b3[3];
    __shared__ float s_mn, s_mx;
    int t = threadIdx.x;

    if (t < 32) { s_w1[t] = rw1[t]; s_b1[t] = rb1[t]; }
    if (t >= 256 && t < 768) s_w2[t - 256] = rw2[t - 256];
    if (t >= 768 && t < 784) s_b2[t - 768] = rb2[t - 768];
    if (t >= 800 && t < 848) s_w3[t - 800] = rw3[t - 800];
    if (t >= 864 && t < 867) s_b3[t - 864] = rb3[t - 864];
    if (t < NBLK) { g_need1[t] = 0; g_need2[t] = 0; }

    float mn = FLT_MAX, mx = -FLT_MAX;
    for (int i = t; i < BROWS; i += 1024) {
        float v = unc[i];
        mn = fminf(mn, v); mx = fmaxf(mx, v);
    }
    smin[t] = mn; smax[t] = mx;
    __syncthreads();
    for (int s = 512; s > 0; s >>= 1) {
        if (t < s) {
            smin[t] = fminf(smin[t], smin[t + s]);
            smax[t] = fmaxf(smax[t], smax[t + s]);
        }
        __syncthreads();
    }
    if (t == 0) { s_mn = smin[0]; s_mx = smax[0]; }
    __syncthreads();

    float vmn = s_mn, vmx = s_mx;
    for (int i = t; i < BROWS; i += 1024) {
        float u = (unc[i] - vmn) / (vmx - vmn + 1e-8f);
        float h1[32];
#pragma unroll
        for (int j = 0; j < 32; j++) h1[j] = fmaxf(fmaf(u, s_w1[j], s_b1[j]), 0.f);
        float h2[16];
#pragma unroll
        for (int j = 0; j < 16; j++) {
            float a = s_b2[j];
#pragma unroll
            for (int k = 0; k < 32; k++) a = fmaf(h1[k], s_w2[k * 16 + j], a);
            h2[j] = fmaxf(a, 0.f);
        }
        float l[3];
#pragma unroll
        for (int j = 0; j < 3; j++) {
            float a = s_b3[j];
#pragma unroll
            for (int k = 0; k < 16; k++) a = fmaf(h2[k], s_w3[k * 3 + j], a);
            l[j] = a;
        }
        int r = 0; float best = l[0];
        if (l[1] > best) { best = l[1]; r = 1; }
        if (l[2] > best) { best = l[2]; r = 2; }
        g_route[i]  = r;
        out_mask[i] = (float)r;
        if (r >= 1) atomicOr(&g_need1[i >> 7], 1);
        if (r == 2) atomicOr(&g_need2[i >> 7], 1);
    }
}

// ---------------------------------------------------------------------------
// prep: x -> g_X (fp16);  W[l][k][n] -> g_Wt[l][n][k] (fp16)
// ---------------------------------------------------------------------------
__global__ void convx_kernel(const float* __restrict__ x) {
    size_t i = ((size_t)blockIdx.x * 256 + threadIdx.x) * 8;
    float4 v0 = *(const float4*)(x + i);
    float4 v1 = *(const float4*)(x + i + 4);
    uint4 o;
    __half2* ho = (__half2*)&o;
    ho[0] = __floats2half2_rn(v0.x, v0.y);
    ho[1] = __floats2half2_rn(v0.z, v0.w);
    ho[2] = __floats2half2_rn(v1.x, v1.y);
    ho[3] = __floats2half2_rn(v1.z, v1.w);
    *(uint4*)(g_X + i) = o;
}
__global__ void transW_kernel(const float* __restrict__ Ws) {
    __shared__ float tile[32][33];
    int l = blockIdx.z;
    int n0 = blockIdx.x * 32, k0 = blockIdx.y * 32;
    const float* Wl = Ws + (size_t)l * DIM * DIM;
#pragma unroll
    for (int i = 0; i < 4; i++)
        tile[threadIdx.y + i * 8][threadIdx.x] =
            Wl[(size_t)(k0 + threadIdx.y + i * 8) * DIM + n0 + threadIdx.x];
    __syncthreads();
    __half* Wt = g_Wt + (size_t)l * DIM * DIM;
#pragma unroll
    for (int i = 0; i < 4; i++) {
        int n = n0 + threadIdx.y + i * 8;
        Wt[(size_t)n * DIM + k0 + threadIdx.x] =
            __float2half_rn(tile[threadIdx.x][threadIdx.y + i * 8]);
    }
}

// ---------------------------------------------------------------------------
// FP16 mma.sync m16n8k16 GEMM, 4-stage cp.async, ldmatrix fragments.
// CTA 128x128x32, 256 threads (8 warps 2x4), warp tile 64x32, 2 CTAs/SM.
// ---------------------------------------------------------------------------
__global__ __launch_bounds__(NTHREADS, 2)
void gemm_kernel(const float* __restrict__ ball, float* __restrict__ outp,
                 int layerIdx, int abuf, int hbuf, int outLevel, int needSel) {
    int bn = blockIdx.x, bm = blockIdx.y;
    if (needSel == 1 && !g_need1[bm]) return;
    if (needSel == 2 && !g_need2[bm]) return;

    extern __shared__ char smem[];
    uint32_t smem_base = smem_u32(smem);

    const __half* A = (abuf == 0) ? g_X : (abuf == 1 ? g_H0 : (abuf == 2 ? g_H1 : g_H2));
    __half* Hptr = (hbuf == 1) ? g_H0 : (hbuf == 2 ? g_H1 : (hbuf == 3 ? g_H2 : nullptr));
    const float* bias = ball + layerIdx * DIM;
    const char* aSrc = (const char*)(A + (size_t)bm * BM * DIM);
    const char* bSrc = (const char*)(g_Wt + (size_t)layerIdx * DIM * DIM + (size_t)bn * BN * DIM);

    int tid  = threadIdx.x;
    int warp = tid >> 5, lane = tid & 31;
    int wm = warp >> 2, wn = warp & 3;     // 2x4 warp grid, 64x32 per warp
    int gq = lane >> 2, tr = lane & 3;

    // ldmatrix lane addressing (m = lane>>3)
    int a_row  = ((lane >> 3) & 1) * 8 + (lane & 7);  // (m&1)*8 + row
    int a_colB = (lane >> 4) * 16;                    // (m>>1)*16B (k half)
    int b_row  = (lane >> 4) * 8 + (lane & 7);        // (m>>1)*8 + n-row
    int b_colB = ((lane >> 3) & 1) * 16;              // (m&1)*16B (k half)

    float acc[4][4][4];
#pragma unroll
    for (int i = 0; i < 4; i++)
#pragma unroll
        for (int j = 0; j < 4; j++)
#pragma unroll
            for (int r = 0; r < 4; r++) acc[i][j][r] = 0.f;

    // --- async load issuer: 4 x 16B cp.async per thread per stage ---
    auto issue = [&](int c) {
        int slot = c & (NSTAGE - 1);
        uint32_t ab = smem_base + slot * STAGE_BYTES;
        uint32_t bb = ab + A_SM_BYTES;
        #pragma unroll
        for (int i = 0; i < 2; i++) {
            int g = tid + i * NTHREADS;
            int r = g >> 2, gc = g & 3;
            CP_ASYNC16(ab + (uint32_t)(r * T_STRIDE + gc * 16),
                       aSrc + (size_t)r * (DIM * 2) + (size_t)c * (BK * 2) + gc * 16);
        }
        #pragma unroll
        for (int i = 0; i < 2; i++) {
            int g = tid + i * NTHREADS;
            int r = g >> 2, gc = g & 3;
            CP_ASYNC16(bb + (uint32_t)(r * T_STRIDE + gc * 16),
                       bSrc + (size_t)r * (DIM * 2) + (size_t)c * (BK * 2) + gc * 16);
        }
        asm volatile("cp.async.commit_group;" ::: "memory");
    };

    issue(0);
    issue(1);
    issue(2);

    for (int c = 0; c < NCH; c++) {
        if (c + 2 < NCH)      asm volatile("cp.async.wait_group 2;" ::: "memory");
        else if (c + 1 < NCH) asm volatile("cp.async.wait_group 1;" ::: "memory");
        else                  asm volatile("cp.async.wait_group 0;" ::: "memory");
        __syncthreads();
        if (c + 3 < NCH) issue(c + 3);

        int slot = c & (NSTAGE - 1);
        uint32_t aBase = smem_base + slot * STAGE_BYTES
                       + (uint32_t)((wm * 64 + a_row) * T_STRIDE + a_colB);
        uint32_t bBase = smem_base + slot * STAGE_BYTES + A_SM_BYTES
                       + (uint32_t)((wn * 32 + b_row) * T_STRIDE + b_colB);

#pragma unroll
        for (int ks = 0; ks < 2; ks++) {        // two k16 steps per BK=32
            uint32_t af[4][4], bf[4][2];
#pragma unroll
            for (int i = 0; i < 4; i++)
                LDSM_X4(af[i][0], af[i][1], af[i][2], af[i][3],
                        aBase + (uint32_t)(i * 16 * T_STRIDE + ks * 32));
#pragma unroll
            for (int jp = 0; jp < 2; jp++)
                LDSM_X4(bf[2 * jp][0], bf[2 * jp][1], bf[2 * jp + 1][0], bf[2 * jp + 1][1],
                        bBase + (uint32_t)(jp * 16 * T_STRIDE + ks * 32));
#pragma unroll
            for (int i = 0; i < 4; i++)
#pragma unroll
                for (int j = 0; j < 4; j++) {
                    asm volatile(
                        "mma.sync.aligned.m16n8k16.row.col.f32.f16.f16.f32 "
                        "{%0,%1,%2,%3}, {%4,%5,%6,%7}, {%8,%9}, {%0,%1,%2,%3};"
                        : "+f"(acc[i][j][0]), "+f"(acc[i][j][1]),
                          "+f"(acc[i][j][2]), "+f"(acc[i][j][3])
                        : "r"(af[i][0]), "r"(af[i][1]), "r"(af[i][2]), "r"(af[i][3]),
                          "r"(bf[j][0]), "r"(bf[j][1]));
                }
        }
        // no trailing barrier needed: next iter's barrier precedes its issue,
        // and issue(c+3) writes a slot whose readers all passed that barrier.
    }

    // ---- epilogue: bias + GELU; H stored fp16, routed rows -> out (fp32) ----
    int rbase = bm * BM + wm * 64;
    int cbase = bn * BN + wn * 32;
#pragma unroll
    for (int i = 0; i < 4; i++) {
        int row0 = rbase + i * 16 + gq;
        int row1 = row0 + 8;
        int rt0 = g_route[row0], rt1 = g_route[row1];
#pragma unroll
        for (int j = 0; j < 4; j++) {
            int col = cbase + j * 8 + 2 * tr;
            float2 bb = *(const float2*)(bias + col);
            float v00 = gelu_f(acc[i][j][0] + bb.x);
            float v01 = gelu_f(acc[i][j][1] + bb.y);
            float v10 = gelu_f(acc[i][j][2] + bb.x);
            float v11 = gelu_f(acc[i][j][3] + bb.y);
            if (Hptr) {
                *(__half2*)&Hptr[(size_t)row0 * DIM + col] = __floats2half2_rn(v00, v01);
                *(__half2*)&Hptr[(size_t)row1 * DIM + col] = __floats2half2_rn(v10, v11);
            }
            if (outp) {
                if (rt0 == outLevel) *(float2*)&outp[(size_t)row0 * DIM + col] = make_float2(v00, v01);
                if (rt1 == outLevel) *(float2*)&outp[(size_t)row1 * DIM + col] = make_float2(v10, v11);
            }
        }
    }
}

// ---------------------------------------------------------------------------
extern "C" void kernel_launch(void* const* d_in, const int* in_sizes, int n_in,
                              void* d_out, int out_size) {
    const float* x   = (const float*)d_in[0];
    const float* unc = (const float*)d_in[1];
    const float* Ws  = (const float*)d_in[2];
    const float* bs  = (const float*)d_in[3];
    const float* rw1 = (const float*)d_in[4];
    const float* rb1 = (const float*)d_in[5];
    const float* rw2 = (const float*)d_in[6];
    const float* rb2 = (const float*)d_in[7];
    const float* rw3 = (const float*)d_in[8];
    const float* rb3 = (const float*)d_in[9];

    float* out  = (float*)d_out;
    float* mask = out + (size_t)BROWS * DIM;

    cudaFuncSetAttribute(gemm_kernel, cudaFuncAttributeMaxDynamicSharedMemorySize, SMEM_TOTAL);

    // launch order keeps L0 GEMM at ncu's captured slot (index 3)
    route_fused_kernel<<<1, 1024>>>(unc, rw1, rb1, rw2, rb2, rw3, rb3, mask);
    convx_kernel<<<(BROWS * DIM) / (256 * 8), 256>>>(x);
    transW_kernel<<<dim3(64, 64, 4), dim3(32, 8)>>>(Ws);

    dim3 grid(DIM / BN, BROWS / BM);  // (16, 64)
    // L0: in=g_X, H=g_H0, rows route==0 -> out
    gemm_kernel<<<grid, NTHREADS, SMEM_TOTAL>>>(bs, out,     0, 0, 1, 0,  0);
    // L1: in=H0, H=H1, rows route==1 -> out ; skip tiles with no route>=1
    gemm_kernel<<<grid, NTHREADS, SMEM_TOTAL>>>(bs, out,     1, 1, 2, 1,  1);
    // L2: in=H1, H=H2 ; skip tiles with no route==2
    gemm_kernel<<<grid, NTHREADS, SMEM_TOTAL>>>(bs, nullptr, 2, 2, 3, -1, 2);
    // L3: in=H2, rows route==2 -> out ; skip tiles with no route==2
    gemm_kernel<<<grid, NTHREADS, SMEM_TOTAL>>>(bs, out,     3, 3, 0, 2,  2);
}

// round 10
// speedup vs baseline: 2.0417x; 1.0965x over previous
#include <cuda_runtime.h>
#include <cuda_fp16.h>
#include <cstdint>
#include <cfloat>

#define BROWS 8192
#define DIM   2048
#define NBLK  (BROWS/128)

#define BM 128
#define BN 128
#define BK 64
#define NCH (DIM/BK)              // 32 k-iterations
// fp16 tiles: 128 rows x 64 fp16 (128B) padded to 144B stride — LDSM conflict-free
#define T_STRIDE 144
#define T_SM_BYTES (128*T_STRIDE)       // 18432
#define A_SM_BYTES T_SM_BYTES
#define STAGE_BYTES (2*T_SM_BYTES)      // 36864
#define NSTAGE 3
#define SMEM_TOTAL (NSTAGE*STAGE_BYTES) // 110592

#define NTHREADS 256              // 8 warps, 2x4 grid of 64x32 warp tiles

// ------------------------- persistent device scratch -------------------------
__device__ __align__(16) __half g_X [(size_t)BROWS * DIM];     // fp16 x
__device__ __align__(16) __half g_Wt[(size_t)4 * DIM * DIM];   // fp16 W^T: [l][n][k]
__device__ __align__(16) __half g_H0[(size_t)BROWS * DIM];
__device__ __align__(16) __half g_H1[(size_t)BROWS * DIM];
__device__ __align__(16) __half g_H2[(size_t)BROWS * DIM];
__device__ int g_route[BROWS];
__device__ int g_need1[NBLK];
__device__ int g_need2[NBLK];

// ------------------------------- helpers --------------------------------
__device__ __forceinline__ uint32_t smem_u32(const void* p) {
    uint32_t a;
    asm("{ .reg .u64 t; cvta.to.shared.u64 t, %1; cvt.u32.u64 %0, t; }" : "=r"(a) : "l"(p));
    return a;
}
#define CP_ASYNC16(dst, src) \
    asm volatile("cp.async.cg.shared.global [%0], [%1], 16;" :: "r"(dst), "l"(src) : "memory")
#define LDSM_X4(r0, r1, r2, r3, addr) \
    asm volatile("ldmatrix.sync.aligned.m8n8.x4.shared.b16 {%0,%1,%2,%3}, [%4];" \
                 : "=r"(r0), "=r"(r1), "=r"(r2), "=r"(r3) : "r"(addr))

__device__ __forceinline__ float gelu_f(float x) {
    float x3 = x * x * x;
    float t = tanhf(0.7978845608028654f * (x + 0.044715f * x3));
    return 0.5f * x * (1.f + t);
}

// ---------------------------------------------------------------------------
// Fused: min/max + router MLP + tile flags. One block, 1024 threads.
// ---------------------------------------------------------------------------
__global__ __launch_bounds__(1024)
void route_fused_kernel(const float* __restrict__ unc,
                        const float* __restrict__ rw1, const float* __restrict__ rb1,
                        const float* __restrict__ rw2, const float* __restrict__ rb2,
                        const float* __restrict__ rw3, const float* __restrict__ rb3,
                        float* __restrict__ out_mask) {
    __shared__ float smin[1024], smax[1024];
    __shared__ float s_w1[32], s_b1[32], s_w2[512], s_b2[16], s_w3[48], s_b3[3];
    __shared__ float s_mn, s_mx;
    int t = threadIdx.x;

    if (t < 32) { s_w1[t] = rw1[t]; s_b1[t] = rb1[t]; }
    if (t >= 256 && t < 768) s_w2[t - 256] = rw2[t - 256];
    if (t >= 768 && t < 784) s_b2[t - 768] = rb2[t - 768];
    if (t >= 800 && t < 848) s_w3[t - 800] = rw3[t - 800];
    if (t >= 864 && t < 867) s_b3[t - 864] = rb3[t - 864];
    if (t < NBLK) { g_need1[t] = 0; g_need2[t] = 0; }

    float mn = FLT_MAX, mx = -FLT_MAX;
    for (int i = t; i < BROWS; i += 1024) {
        float v = unc[i];
        mn = fminf(mn, v); mx = fmaxf(mx, v);
    }
    smin[t] = mn; smax[t] = mx;
    __syncthreads();
    for (int s = 512; s > 0; s >>= 1) {
        if (t < s) {
            smin[t] = fminf(smin[t], smin[t + s]);
            smax[t] = fmaxf(smax[t], smax[t + s]);
        }
        __syncthreads();
    }
    if (t == 0) { s_mn = smin[0]; s_mx = smax[0]; }
    __syncthreads();

    float vmn = s_mn, vmx = s_mx;
    for (int i = t; i < BROWS; i += 1024) {
        float u = (unc[i] - vmn) / (vmx - vmn + 1e-8f);
        float h1[32];
#pragma unroll
        for (int j = 0; j < 32; j++) h1[j] = fmaxf(fmaf(u, s_w1[j], s_b1[j]), 0.f);
        float h2[16];
#pragma unroll
        for (int j = 0; j < 16; j++) {
            float a = s_b2[j];
#pragma unroll
            for (int k = 0; k < 32; k++) a = fmaf(h1[k], s_w2[k * 16 + j], a);
            h2[j] = fmaxf(a, 0.f);
        }
        float l[3];
#pragma unroll
        for (int j = 0; j < 3; j++) {
            float a = s_b3[j];
#pragma unroll
            for (int k = 0; k < 16; k++) a = fmaf(h2[k], s_w3[k * 3 + j], a);
            l[j] = a;
        }
        int r = 0; float best = l[0];
        if (l[1] > best) { best = l[1]; r = 1; }
        if (l[2] > best) { best = l[2]; r = 2; }
        g_route[i]  = r;
        out_mask[i] = (float)r;
        if (r >= 1) atomicOr(&g_need1[i >> 7], 1);
        if (r == 2) atomicOr(&g_need2[i >> 7], 1);
    }
}

// ---------------------------------------------------------------------------
// prep: x -> g_X (fp16);  W[l][k][n] -> g_Wt[l][n][k] (fp16)
// ---------------------------------------------------------------------------
__global__ void convx_kernel(const float* __restrict__ x) {
    size_t i = ((size_t)blockIdx.x * 256 + threadIdx.x) * 8;
    float4 v0 = *(const float4*)(x + i);
    float4 v1 = *(const float4*)(x + i + 4);
    uint4 o;
    __half2* ho = (__half2*)&o;
    ho[0] = __floats2half2_rn(v0.x, v0.y);
    ho[1] = __floats2half2_rn(v0.z, v0.w);
    ho[2] = __floats2half2_rn(v1.x, v1.y);
    ho[3] = __floats2half2_rn(v1.z, v1.w);
    *(uint4*)(g_X + i) = o;
}
__global__ void transW_kernel(const float* __restrict__ Ws) {
    __shared__ float tile[32][33];
    int l = blockIdx.z;
    int n0 = blockIdx.x * 32, k0 = blockIdx.y * 32;
    const float* Wl = Ws + (size_t)l * DIM * DIM;
#pragma unroll
    for (int i = 0; i < 4; i++)
        tile[threadIdx.y + i * 8][threadIdx.x] =
            Wl[(size_t)(k0 + threadIdx.y + i * 8) * DIM + n0 + threadIdx.x];
    __syncthreads();
    __half* Wt = g_Wt + (size_t)l * DIM * DIM;
#pragma unroll
    for (int i = 0; i < 4; i++) {
        int n = n0 + threadIdx.y + i * 8;
        Wt[(size_t)n * DIM + k0 + threadIdx.x] =
            __float2half_rn(tile[threadIdx.x][threadIdx.y + i * 8]);
    }
}

// ---------------------------------------------------------------------------
// FP16 mma.sync m16n8k16 GEMM, BK=64, 3-stage cp.async, ldmatrix fragments.
// CTA 128x128x64, 256 threads (8 warps 2x4), warp tile 64x32, 2 CTAs/SM.
// ---------------------------------------------------------------------------
__global__ __launch_bounds__(NTHREADS, 2)
void gemm_kernel(const float* __restrict__ ball, float* __restrict__ outp,
                 int layerIdx, int abuf, int hbuf, int outLevel, int needSel) {
    int bn = blockIdx.x, bm = blockIdx.y;
    if (needSel == 1 && !g_need1[bm]) return;
    if (needSel == 2 && !g_need2[bm]) return;

    extern __shared__ char smem[];
    uint32_t smem_base = smem_u32(smem);

    const __half* A = (abuf == 0) ? g_X : (abuf == 1 ? g_H0 : (abuf == 2 ? g_H1 : g_H2));
    __half* Hptr = (hbuf == 1) ? g_H0 : (hbuf == 2 ? g_H1 : (hbuf == 3 ? g_H2 : nullptr));
    const float* bias = ball + layerIdx * DIM;
    const char* aSrc = (const char*)(A + (size_t)bm * BM * DIM);
    const char* bSrc = (const char*)(g_Wt + (size_t)layerIdx * DIM * DIM + (size_t)bn * BN * DIM);

    int tid  = threadIdx.x;
    int warp = tid >> 5, lane = tid & 31;
    int wm = warp >> 2, wn = warp & 3;     // 2x4 warp grid, 64x32 per warp
    int gq = lane >> 2, tr = lane & 3;

    // ldmatrix lane addressing (m = lane>>3)
    int a_row  = ((lane >> 3) & 1) * 8 + (lane & 7);  // (m&1)*8 + row
    int a_colB = (lane >> 4) * 16;                    // (m>>1)*16B (k half)
    int b_row  = (lane >> 4) * 8 + (lane & 7);        // (m>>1)*8 + n-row
    int b_colB = ((lane >> 3) & 1) * 16;              // (m&1)*16B (k half)

    float acc[4][4][4];
#pragma unroll
    for (int i = 0; i < 4; i++)
#pragma unroll
        for (int j = 0; j < 4; j++)
#pragma unroll
            for (int r = 0; r < 4; r++) acc[i][j][r] = 0.f;

    // --- async load issuer: 8 x 16B cp.async per thread per stage ---
    // tile rows are 128B of data (8 granules) at 144B stride
    auto issue = [&](int c) {
        int slot = c % NSTAGE;
        uint32_t ab = smem_base + slot * STAGE_BYTES;
        uint32_t bb = ab + A_SM_BYTES;
        #pragma unroll
        for (int i = 0; i < 4; i++) {
            int g = tid + i * NTHREADS;
            int r = g >> 3, gc = g & 7;
            CP_ASYNC16(ab + (uint32_t)(r * T_STRIDE + gc * 16),
                       aSrc + (size_t)r * (DIM * 2) + (size_t)c * (BK * 2) + gc * 16);
        }
        #pragma unroll
        for (int i = 0; i < 4; i++) {
            int g = tid + i * NTHREADS;
            int r = g >> 3, gc = g & 7;
            CP_ASYNC16(bb + (uint32_t)(r * T_STRIDE + gc * 16),
                       bSrc + (size_t)r * (DIM * 2) + (size_t)c * (BK * 2) + gc * 16);
        }
        asm volatile("cp.async.commit_group;" ::: "memory");
    };

    issue(0);
    issue(1);

    for (int c = 0; c < NCH; c++) {
        if (c < NCH - 1) asm volatile("cp.async.wait_group 1;" ::: "memory");
        else             asm volatile("cp.async.wait_group 0;" ::: "memory");
        __syncthreads();
        if (c + 2 < NCH) issue(c + 2);

        int slot = c % NSTAGE;
        uint32_t aBase = smem_base + slot * STAGE_BYTES
                       + (uint32_t)((wm * 64 + a_row) * T_STRIDE + a_colB);
        uint32_t bBase = smem_base + slot * STAGE_BYTES + A_SM_BYTES
                       + (uint32_t)((wn * 32 + b_row) * T_STRIDE + b_colB);

#pragma unroll
        for (int ks = 0; ks < 4; ks++) {        // four k16 steps per BK=64
            uint32_t af[4][4], bf[4][2];
#pragma unroll
            for (int i = 0; i < 4; i++)
                LDSM_X4(af[i][0], af[i][1], af[i][2], af[i][3],
                        aBase + (uint32_t)(i * 16 * T_STRIDE + ks * 32));
#pragma unroll
            for (int jp = 0; jp < 2; jp++)
                LDSM_X4(bf[2 * jp][0], bf[2 * jp][1], bf[2 * jp + 1][0], bf[2 * jp + 1][1],
                        bBase + (uint32_t)(jp * 16 * T_STRIDE + ks * 32));
#pragma unroll
            for (int i = 0; i < 4; i++)
#pragma unroll
                for (int j = 0; j < 4; j++) {
                    asm volatile(
                        "mma.sync.aligned.m16n8k16.row.col.f32.f16.f16.f32 "
                        "{%0,%1,%2,%3}, {%4,%5,%6,%7}, {%8,%9}, {%0,%1,%2,%3};"
                        : "+f"(acc[i][j][0]), "+f"(acc[i][j][1]),
                          "+f"(acc[i][j][2]), "+f"(acc[i][j][3])
                        : "r"(af[i][0]), "r"(af[i][1]), "r"(af[i][2]), "r"(af[i][3]),
                          "r"(bf[j][0]), "r"(bf[j][1]));
                }
        }
    }

    // ---- epilogue: bias + GELU; H stored fp16, routed rows -> out (fp32) ----
    int rbase = bm * BM + wm * 64;
    int cbase = bn * BN + wn * 32;
#pragma unroll
    for (int i = 0; i < 4; i++) {
        int row0 = rbase + i * 16 + gq;
        int row1 = row0 + 8;
        int rt0 = g_route[row0], rt1 = g_route[row1];
#pragma unroll
        for (int j = 0; j < 4; j++) {
            int col = cbase + j * 8 + 2 * tr;
            float2 bb = *(const float2*)(bias + col);
            float v00 = gelu_f(acc[i][j][0] + bb.x);
            float v01 = gelu_f(acc[i][j][1] + bb.y);
            float v10 = gelu_f(acc[i][j][2] + bb.x);
            float v11 = gelu_f(acc[i][j][3] + bb.y);
            if (Hptr) {
                *(__half2*)&Hptr[(size_t)row0 * DIM + col] = __floats2half2_rn(v00, v01);
                *(__half2*)&Hptr[(size_t)row1 * DIM + col] = __floats2half2_rn(v10, v11);
            }
            if (outp) {
                if (rt0 == outLevel) *(float2*)&outp[(size_t)row0 * DIM + col] = make_float2(v00, v01);
                if (rt1 == outLevel) *(float2*)&outp[(size_t)row1 * DIM + col] = make_float2(v10, v11);
            }
        }
    }
}

// ---------------------------------------------------------------------------
extern "C" void kernel_launch(void* const* d_in, const int* in_sizes, int n_in,
                              void* d_out, int out_size) {
    const float* x   = (const float*)d_in[0];
    const float* unc = (const float*)d_in[1];
    const float* Ws  = (const float*)d_in[2];
    const float* bs  = (const float*)d_in[3];
    const float* rw1 = (const float*)d_in[4];
    const float* rb1 = (const float*)d_in[5];
    const float* rw2 = (const float*)d_in[6];
    const float* rb2 = (const float*)d_in[7];
    const float* rw3 = (const float*)d_in[8];
    const float* rb3 = (const float*)d_in[9];

    float* out  = (float*)d_out;
    float* mask = out + (size_t)BROWS * DIM;

    cudaFuncSetAttribute(gemm_kernel, cudaFuncAttributeMaxDynamicSharedMemorySize, SMEM_TOTAL);

    // launch order keeps L0 GEMM at ncu's captured slot (index 3)
    route_fused_kernel<<<1, 1024>>>(unc, rw1, rb1, rw2, rb2, rw3, rb3, mask);
    convx_kernel<<<(BROWS * DIM) / (256 * 8), 256>>>(x);
    transW_kernel<<<dim3(64, 64, 4), dim3(32, 8)>>>(Ws);

    dim3 grid(DIM / BN, BROWS / BM);  // (16, 64)
    // L0: in=g_X, H=g_H0, rows route==0 -> out
    gemm_kernel<<<grid, NTHREADS, SMEM_TOTAL>>>(bs, out,     0, 0, 1, 0,  0);
    // L1: in=H0, H=H1, rows route==1 -> out ; skip tiles with no route>=1
    gemm_kernel<<<grid, NTHREADS, SMEM_TOTAL>>>(bs, out,     1, 1, 2, 1,  1);
    // L2: in=H1, H=H2 ; skip tiles with no route==2
    gemm_kernel<<<grid, NTHREADS, SMEM_TOTAL>>>(bs, nullptr, 2, 2, 3, -1, 2);
    // L3: in=H2, rows route==2 -> out ; skip tiles with no route==2
    gemm_kernel<<<grid, NTHREADS, SMEM_TOTAL>>>(bs, out,     3, 3, 0, 2,  2);
}

// round 11
// speedup vs baseline: 2.1230x; 1.0398x over previous
#include <cuda_runtime.h>
#include <cuda_fp16.h>
#include <cstdint>
#include <cfloat>

#define BROWS 8192
#define DIM   2048
#define NBLK  (BROWS/128)

#define BM 128
#define BN 128
#define BK 64
#define NCH (DIM/BK)              // 32 k-iterations
// fp16 tiles: 128 rows x 64 fp16 (128B) padded to 144B stride — LDSM conflict-free
#define T_STRIDE 144
#define T_SM_BYTES (128*T_STRIDE)       // 18432
#define A_SM_BYTES T_SM_BYTES
#define STAGE_BYTES (2*T_SM_BYTES)      // 36864
#define NSTAGE 3
#define SMEM_TOTAL (NSTAGE*STAGE_BYTES) // 110592

#define NTHREADS 256              // 8 warps, 2x4 grid of 64x32 warp tiles

#define TILES_PER_LAYER 1024      // 64 bm x 16 bn
#define TOTAL_TILES (4*TILES_PER_LAYER)

// ------------------------- persistent device scratch -------------------------
__device__ __align__(16) __half g_X [(size_t)BROWS * DIM];     // fp16 x
__device__ __align__(16) __half g_Wt[(size_t)4 * DIM * DIM];   // fp16 W^T: [l][n][k]
__device__ __align__(16) __half g_H0[(size_t)BROWS * DIM];
__device__ __align__(16) __half g_H1[(size_t)BROWS * DIM];
__device__ __align__(16) __half g_H2[(size_t)BROWS * DIM];
__device__ int g_route[BROWS];
__device__ int g_ticket;
__device__ int g_done[4][NBLK];   // per-layer, per-row-block completion counters

// ------------------------------- helpers --------------------------------
__device__ __forceinline__ uint32_t smem_u32(const void* p) {
    uint32_t a;
    asm("{ .reg .u64 t; cvta.to.shared.u64 t, %1; cvt.u32.u64 %0, t; }" : "=r"(a) : "l"(p));
    return a;
}
#define CP_ASYNC16(dst, src) \
    asm volatile("cp.async.cg.shared.global [%0], [%1], 16;" :: "r"(dst), "l"(src) : "memory")
#define LDSM_X4(r0, r1, r2, r3, addr) \
    asm volatile("ldmatrix.sync.aligned.m8n8.x4.shared.b16 {%0,%1,%2,%3}, [%4];" \
                 : "=r"(r0), "=r"(r1), "=r"(r2), "=r"(r3) : "r"(addr))

__device__ __forceinline__ float gelu_f(float x) {
    float x3 = x * x * x;
    float t = tanhf(0.7978845608028654f * (x + 0.044715f * x3));
    return 0.5f * x * (1.f + t);
}

// ---------------------------------------------------------------------------
// Fused: min/max + router MLP + scheduler-state reset. One block, 1024 thr.
// ---------------------------------------------------------------------------
__global__ __launch_bounds__(1024)
void route_fused_kernel(const float* __restrict__ unc,
                        const float* __restrict__ rw1, const float* __restrict__ rb1,
                        const float* __restrict__ rw2, const float* __restrict__ rb2,
                        const float* __restrict__ rw3, const float* __restrict__ rb3,
                        float* __restrict__ out_mask) {
    __shared__ float smin[1024], smax[1024];
    __shared__ float s_w1[32], s_b1[32], s_w2[512], s_b2[16], s_w3[48], s_b3[3];
    __shared__ float s_mn, s_mx;
    int t = threadIdx.x;

    if (t < 32) { s_w1[t] = rw1[t]; s_b1[t] = rb1[t]; }
    if (t >= 256 && t < 768) s_w2[t - 256] = rw2[t - 256];
    if (t >= 768 && t < 784) s_b2[t - 768] = rb2[t - 768];
    if (t >= 800 && t < 848) s_w3[t - 800] = rw3[t - 800];
    if (t >= 864 && t < 867) s_b3[t - 864] = rb3[t - 864];
    // reset persistent-scheduler state (graph-replay safe)
    if (t < 4 * NBLK) ((int*)g_done)[t] = 0;
    if (t == 0) g_ticket = 0;

    float mn = FLT_MAX, mx = -FLT_MAX;
    for (int i = t; i < BROWS; i += 1024) {
        float v = unc[i];
        mn = fminf(mn, v); mx = fmaxf(mx, v);
    }
    smin[t] = mn; smax[t] = mx;
    __syncthreads();
    for (int s = 512; s > 0; s >>= 1) {
        if (t < s) {
            smin[t] = fminf(smin[t], smin[t + s]);
            smax[t] = fmaxf(smax[t], smax[t + s]);
        }
        __syncthreads();
    }
    if (t == 0) { s_mn = smin[0]; s_mx = smax[0]; }
    __syncthreads();

    float vmn = s_mn, vmx = s_mx;
    for (int i = t; i < BROWS; i += 1024) {
        float u = (unc[i] - vmn) / (vmx - vmn + 1e-8f);
        float h1[32];
#pragma unroll
        for (int j = 0; j < 32; j++) h1[j] = fmaxf(fmaf(u, s_w1[j], s_b1[j]), 0.f);
        float h2[16];
#pragma unroll
        for (int j = 0; j < 16; j++) {
            float a = s_b2[j];
#pragma unroll
            for (int k = 0; k < 32; k++) a = fmaf(h1[k], s_w2[k * 16 + j], a);
            h2[j] = fmaxf(a, 0.f);
        }
        float l[3];
#pragma unroll
        for (int j = 0; j < 3; j++) {
            float a = s_b3[j];
#pragma unroll
            for (int k = 0; k < 16; k++) a = fmaf(h2[k], s_w3[k * 3 + j], a);
            l[j] = a;
        }
        int r = 0; float best = l[0];
        if (l[1] > best) { best = l[1]; r = 1; }
        if (l[2] > best) { best = l[2]; r = 2; }
        g_route[i]  = r;
        out_mask[i] = (float)r;
    }
}

// ---------------------------------------------------------------------------
// prep: x -> g_X (fp16);  W[l][k][n] -> g_Wt[l][n][k] (fp16)
// ---------------------------------------------------------------------------
__global__ void convx_kernel(const float* __restrict__ x) {
    size_t i = ((size_t)blockIdx.x * 256 + threadIdx.x) * 8;
    float4 v0 = *(const float4*)(x + i);
    float4 v1 = *(const float4*)(x + i + 4);
    uint4 o;
    __half2* ho = (__half2*)&o;
    ho[0] = __floats2half2_rn(v0.x, v0.y);
    ho[1] = __floats2half2_rn(v0.z, v0.w);
    ho[2] = __floats2half2_rn(v1.x, v1.y);
    ho[3] = __floats2half2_rn(v1.z, v1.w);
    *(uint4*)(g_X + i) = o;
}
__global__ void transW_kernel(const float* __restrict__ Ws) {
    __shared__ float tile[32][33];
    int l = blockIdx.z;
    int n0 = blockIdx.x * 32, k0 = blockIdx.y * 32;
    const float* Wl = Ws + (size_t)l * DIM * DIM;
#pragma unroll
    for (int i = 0; i < 4; i++)
        tile[threadIdx.y + i * 8][threadIdx.x] =
            Wl[(size_t)(k0 + threadIdx.y + i * 8) * DIM + n0 + threadIdx.x];
    __syncthreads();
    __half* Wt = g_Wt + (size_t)l * DIM * DIM;
#pragma unroll
    for (int i = 0; i < 4; i++) {
        int n = n0 + threadIdx.y + i * 8;
        Wt[(size_t)n * DIM + k0 + threadIdx.x] =
            __float2half_rn(tile[threadIdx.x][threadIdx.y + i * 8]);
    }
}

// ---------------------------------------------------------------------------
// Persistent FP16 GEMM: all 4 layers, ticket scheduler + dataflow sync.
// Tile config identical to R10: CTA 128x128x64, 8 warps 64x32, 3-stage, 2 CTA/SM.
// ---------------------------------------------------------------------------
__global__ __launch_bounds__(NTHREADS, 2)
void gemm_persistent(const float* __restrict__ ball, float* __restrict__ outp) {
    extern __shared__ char smem[];
    __shared__ int s_item;
    uint32_t smem_base = smem_u32(smem);

    int tid  = threadIdx.x;
    int warp = tid >> 5, lane = tid & 31;
    int wm = warp >> 2, wn = warp & 3;     // 2x4 warp grid, 64x32 per warp
    int gq = lane >> 2, tr = lane & 3;

    // ldmatrix lane addressing (m = lane>>3)
    int a_row  = ((lane >> 3) & 1) * 8 + (lane & 7);
    int a_colB = (lane >> 4) * 16;
    int b_row  = (lane >> 4) * 8 + (lane & 7);
    int b_colB = ((lane >> 3) & 1) * 16;

    for (;;) {
        if (tid == 0) s_item = atomicAdd(&g_ticket, 1);
        __syncthreads();
        int item = s_item;
        if (item >= TOTAL_TILES) return;

        int layer = item >> 10;
        int rem   = item & 1023;
        int bm = rem >> 4, bn = rem & 15;

        const __half* A; __half* Hptr; int outLevel;
        switch (layer) {
            case 0:  A = g_X;  Hptr = g_H0;    outLevel = 0;  break;
            case 1:  A = g_H0; Hptr = g_H1;    outLevel = 1;  break;
            case 2:  A = g_H1; Hptr = g_H2;    outLevel = -1; break;
            default: A = g_H2; Hptr = nullptr; outLevel = 2;  break;
        }
        const float* bias = ball + layer * DIM;
        const char* aSrc = (const char*)(A + (size_t)bm * BM * DIM);
        const char* bSrc = (const char*)(g_Wt + (size_t)layer * DIM * DIM + (size_t)bn * BN * DIM);

        // dataflow dependency: need row-block bm of previous layer complete
        if (layer > 0) {
            if (tid == 0) {
                volatile int* d = &g_done[layer - 1][bm];
                while (*d < 16) __nanosleep(64);
                __threadfence();
            }
            __syncthreads();
        }

        float acc[4][4][4];
#pragma unroll
        for (int i = 0; i < 4; i++)
#pragma unroll
            for (int j = 0; j < 4; j++)
#pragma unroll
                for (int r = 0; r < 4; r++) acc[i][j][r] = 0.f;

        auto issue = [&](int c) {
            int slot = c % NSTAGE;
            uint32_t ab = smem_base + slot * STAGE_BYTES;
            uint32_t bb = ab + A_SM_BYTES;
            #pragma unroll
            for (int i = 0; i < 4; i++) {
                int g = tid + i * NTHREADS;
                int r = g >> 3, gc = g & 7;
                CP_ASYNC16(ab + (uint32_t)(r * T_STRIDE + gc * 16),
                           aSrc + (size_t)r * (DIM * 2) + (size_t)c * (BK * 2) + gc * 16);
            }
            #pragma unroll
            for (int i = 0; i < 4; i++) {
                int g = tid + i * NTHREADS;
                int r = g >> 3, gc = g & 7;
                CP_ASYNC16(bb + (uint32_t)(r * T_STRIDE + gc * 16),
                           bSrc + (size_t)r * (DIM * 2) + (size_t)c * (BK * 2) + gc * 16);
            }
            asm volatile("cp.async.commit_group;" ::: "memory");
        };

        issue(0);
        issue(1);

        for (int c = 0; c < NCH; c++) {
            if (c < NCH - 1) asm volatile("cp.async.wait_group 1;" ::: "memory");
            else             asm volatile("cp.async.wait_group 0;" ::: "memory");
            __syncthreads();
            if (c + 2 < NCH) issue(c + 2);

            int slot = c % NSTAGE;
            uint32_t aBase = smem_base + slot * STAGE_BYTES
                           + (uint32_t)((wm * 64 + a_row) * T_STRIDE + a_colB);
            uint32_t bBase = smem_base + slot * STAGE_BYTES + A_SM_BYTES
                           + (uint32_t)((wn * 32 + b_row) * T_STRIDE + b_colB);

#pragma unroll
            for (int ks = 0; ks < 4; ks++) {        // four k16 steps per BK=64
                uint32_t af[4][4], bf[4][2];
#pragma unroll
                for (int i = 0; i < 4; i++)
                    LDSM_X4(af[i][0], af[i][1], af[i][2], af[i][3],
                            aBase + (uint32_t)(i * 16 * T_STRIDE + ks * 32));
#pragma unroll
                for (int jp = 0; jp < 2; jp++)
                    LDSM_X4(bf[2 * jp][0], bf[2 * jp][1], bf[2 * jp + 1][0], bf[2 * jp + 1][1],
                            bBase + (uint32_t)(jp * 16 * T_STRIDE + ks * 32));
#pragma unroll
                for (int i = 0; i < 4; i++)
#pragma unroll
                    for (int j = 0; j < 4; j++) {
                        asm volatile(
                            "mma.sync.aligned.m16n8k16.row.col.f32.f16.f16.f32 "
                            "{%0,%1,%2,%3}, {%4,%5,%6,%7}, {%8,%9}, {%0,%1,%2,%3};"
                            : "+f"(acc[i][j][0]), "+f"(acc[i][j][1]),
                              "+f"(acc[i][j][2]), "+f"(acc[i][j][3])
                            : "r"(af[i][0]), "r"(af[i][1]), "r"(af[i][2]), "r"(af[i][3]),
                              "r"(bf[j][0]), "r"(bf[j][1]));
                    }
            }
        }

        // ---- epilogue: bias + GELU; H fp16, routed rows -> out (fp32) ----
        int rbase = bm * BM + wm * 64;
        int cbase = bn * BN + wn * 32;
#pragma unroll
        for (int i = 0; i < 4; i++) {
            int row0 = rbase + i * 16 + gq;
            int row1 = row0 + 8;
            int rt0 = g_route[row0], rt1 = g_route[row1];
#pragma unroll
            for (int j = 0; j < 4; j++) {
                int col = cbase + j * 8 + 2 * tr;
                float2 bb = *(const float2*)(bias + col);
                float v00 = gelu_f(acc[i][j][0] + bb.x);
                float v01 = gelu_f(acc[i][j][1] + bb.y);
                float v10 = gelu_f(acc[i][j][2] + bb.x);
                float v11 = gelu_f(acc[i][j][3] + bb.y);
                if (Hptr) {
                    *(__half2*)&Hptr[(size_t)row0 * DIM + col] = __floats2half2_rn(v00, v01);
                    *(__half2*)&Hptr[(size_t)row1 * DIM + col] = __floats2half2_rn(v10, v11);
                }
                if (outLevel >= 0) {
                    if (rt0 == outLevel) *(float2*)&outp[(size_t)row0 * DIM + col] = make_float2(v00, v01);
                    if (rt1 == outLevel) *(float2*)&outp[(size_t)row1 * DIM + col] = make_float2(v10, v11);
                }
            }
        }

        // publish completion of this tile for layer-(l+1) consumers
        __threadfence();
        __syncthreads();
        if (tid == 0 && layer < 3) atomicAdd(&g_done[layer][bm], 1);
    }
}

// ---------------------------------------------------------------------------
extern "C" void kernel_launch(void* const* d_in, const int* in_sizes, int n_in,
                              void* d_out, int out_size) {
    const float* x   = (const float*)d_in[0];
    const float* unc = (const float*)d_in[1];
    const float* Ws  = (const float*)d_in[2];
    const float* bs  = (const float*)d_in[3];
    const float* rw1 = (const float*)d_in[4];
    const float* rb1 = (const float*)d_in[5];
    const float* rw2 = (const float*)d_in[6];
    const float* rb2 = (const float*)d_in[7];
    const float* rw3 = (const float*)d_in[8];
    const float* rb3 = (const float*)d_in[9];

    float* out  = (float*)d_out;
    float* mask = out + (size_t)BROWS * DIM;

    cudaFuncSetAttribute(gemm_persistent, cudaFuncAttributeMaxDynamicSharedMemorySize, SMEM_TOTAL);

    int sms = 148;
    cudaDeviceGetAttribute(&sms, cudaDevAttrMultiProcessorCount, 0);

    // launch order keeps the GEMM at ncu's captured slot (index 3)
    route_fused_kernel<<<1, 1024>>>(unc, rw1, rb1, rw2, rb2, rw3, rb3, mask);
    convx_kernel<<<(BROWS * DIM) / (256 * 8), 256>>>(x);
    transW_kernel<<<dim3(64, 64, 4), dim3(32, 8)>>>(Ws);

    gemm_persistent<<<2 * sms, NTHREADS, SMEM_TOTAL>>>(bs, out);
}